// round 10
// baseline (speedup 1.0000x reference)
#include <cuda_runtime.h>
#include <cuda_fp16.h>
#include <cstdint>

// ---------------------------------------------------------------------------
// Problem constants
// ---------------------------------------------------------------------------
constexpr int kB = 8;
constexpr int kT = 1024;
constexpr int kD = 1024;          // n_embd
constexpr int kH = 16;            // heads
constexpr int kE = 64;            // head size
constexpr int kF = 4096;          // ffn hidden
constexpr int kM = kB * kT;       // 8192 rows
constexpr int kQKVN = 3 * kD;     // 3072

// ---------------------------------------------------------------------------
// Scratch (device globals: allocation-free per harness rules)
// ---------------------------------------------------------------------------
__device__ __align__(16) float  g_ln1f[(size_t)kM * kD];
__device__ __align__(16) __half g_ln1h[(size_t)kM * kD];
__device__ __align__(16) __half g_qkvh[(size_t)kM * kQKVN];
__device__ __align__(16) __half g_atth[(size_t)kM * kD];
__device__ __align__(16) float  g_x2  [(size_t)kM * kD];
__device__ __align__(16) float  g_ln2f[(size_t)kM * kD];
__device__ __align__(16) __half g_ln2h[(size_t)kM * kD];
__device__ __align__(16) __half g_hidh[(size_t)kM * kF];
__device__ __align__(16) __half g_wqkv[(size_t)kQKVN * kD];   // [N=3072][K=1024]
__device__ __align__(16) __half g_wp  [(size_t)kD * kD];      // [N=1024][K=1024]
__device__ __align__(16) __half g_w1t [(size_t)kF * kD];      // [N=4096][K=1024]
__device__ __align__(16) __half g_w2t [(size_t)kD * kF];      // [N=1024][K=4096]

// ---------------------------------------------------------------------------
// Low-level helpers
// ---------------------------------------------------------------------------
__device__ __forceinline__ uint32_t smem_u32(const void* p) {
    uint32_t r;
    asm("{ .reg .u64 t; cvta.to.shared.u64 t, %1; cvt.u32.u64 %0, t; }"
        : "=r"(r) : "l"(p));
    return r;
}

__device__ __forceinline__ void cp_async16(uint32_t dst, const void* src) {
    asm volatile("cp.async.cg.shared.global [%0], [%1], 16;"
                 :: "r"(dst), "l"(src));
}

__device__ __forceinline__ void ldmatrix_x4(uint32_t* r, uint32_t addr) {
    asm volatile("ldmatrix.sync.aligned.m8n8.x4.shared.b16 {%0,%1,%2,%3}, [%4];"
                 : "=r"(r[0]), "=r"(r[1]), "=r"(r[2]), "=r"(r[3]) : "r"(addr));
}

__device__ __forceinline__ void ldmatrix_x4_trans(uint32_t* r, uint32_t addr) {
    asm volatile("ldmatrix.sync.aligned.m8n8.x4.trans.shared.b16 {%0,%1,%2,%3}, [%4];"
                 : "=r"(r[0]), "=r"(r[1]), "=r"(r[2]), "=r"(r[3]) : "r"(addr));
}

__device__ __forceinline__ void mma16816(float* d,
                                         const uint32_t* a, const uint32_t* b) {
    asm volatile(
        "mma.sync.aligned.m16n8k16.row.col.f32.f16.f16.f32 "
        "{%0,%1,%2,%3}, {%4,%5,%6,%7}, {%8,%9}, {%0,%1,%2,%3};"
        : "+f"(d[0]), "+f"(d[1]), "+f"(d[2]), "+f"(d[3])
        : "r"(a[0]), "r"(a[1]), "r"(a[2]), "r"(a[3]), "r"(b[0]), "r"(b[1]));
}

__device__ __forceinline__ uint32_t packh2(float a, float b) {
    __half2 h = __floats2half2_rn(a, b);
    return *reinterpret_cast<uint32_t*>(&h);
}

// ---------------------------------------------------------------------------
// HMMA GEMM: C[M,N] = A_h[M,K] @ B_h[N,K]^T  (+bias) (+res) (relu)
// 128x128 block tile, BK=64, 3-stage cp.async pipeline.
// 128 threads = 4 warps, each owning a 64x64 warp tile (2x2 warp grid):
// per k16-step 8 ldmatrix.x4 feed 32 MMAs (vs 6:16 before).
// Smem tiles: 128 rows x 128B, XOR-swizzled.
// ---------------------------------------------------------------------------
constexpr int GEMM_SMEM = 3 * 32768;   // 96 KB

template <int RELU, int W32, int W16>
__global__ __launch_bounds__(128, 2)
void gemm_mma(const __half* __restrict__ A, const __half* __restrict__ B,
              const float* __restrict__ bias, const float* __restrict__ res,
              float* __restrict__ C32, __half* __restrict__ C16,
              int M, int N, int K)
{
    extern __shared__ char smem[];
    uint32_t sb = smem_u32(smem);

    const int tid  = threadIdx.x;
    const int wid  = tid >> 5;
    const int lane = tid & 31;
    const int wm = (wid & 1) * 64;        // warp row offset in tile
    const int wn = (wid >> 1) * 64;       // warp col offset in tile
    const int row0 = blockIdx.y * 128;
    const int col0 = blockIdx.x * 128;
    const __half* Ab = A + (size_t)row0 * K;
    const __half* Bb = B + (size_t)col0 * K;
    const int nch = K >> 6;               // chunks of K=64

    auto load_chunk = [&](int c, int s) {
        uint32_t base = sb + (uint32_t)s * 32768u;
        const __half* Ap = Ab + c * 64;
        const __half* Bp = Bb + c * 64;
        #pragma unroll
        for (int j = 0; j < 8; j++) {
            int idx = tid + j * 128;              // 0..1023
            int r  = idx >> 3;
            int cc = idx & 7;
            uint32_t off = (uint32_t)(r * 128 + ((cc ^ (r & 7)) << 4));
            cp_async16(base + off,         Ap + (size_t)r * K + cc * 8);
            cp_async16(base + 16384 + off, Bp + (size_t)r * K + cc * 8);
        }
        asm volatile("cp.async.commit_group;" ::: "memory");
    };

    float acc[4][8][4];
    #pragma unroll
    for (int i = 0; i < 4; i++)
        #pragma unroll
        for (int j = 0; j < 8; j++)
            #pragma unroll
            for (int q = 0; q < 4; q++) acc[i][j][q] = 0.f;

    load_chunk(0, 0);
    load_chunk(1, 1);

    for (int i = 0; i < nch; i++) {
        if (i < nch - 1) asm volatile("cp.async.wait_group 1;" ::: "memory");
        else             asm volatile("cp.async.wait_group 0;" ::: "memory");
        __syncthreads();

        if (i + 2 < nch) load_chunk(i + 2, (i + 2) % 3);

        uint32_t abase = sb + (uint32_t)(i % 3) * 32768u;
        uint32_t bbase = abase + 16384;

        #pragma unroll
        for (int kk = 0; kk < 4; kk++) {          // 4 k-steps of 16
            uint32_t af[4][4];
            #pragma unroll
            for (int mt = 0; mt < 4; mt++) {
                int m  = wm + mt * 16 + (lane & 7) + ((lane >> 3) & 1) * 8;
                int kc = kk * 2 + (lane >> 4);
                ldmatrix_x4(af[mt],
                            abase + (uint32_t)(m * 128 + ((kc ^ (m & 7)) << 4)));
            }
            uint32_t bf[4][4];
            #pragma unroll
            for (int nb = 0; nb < 4; nb++) {
                int n  = wn + nb * 16 + (lane & 7) + (lane >> 4) * 8;
                int kc = kk * 2 + ((lane >> 3) & 1);
                ldmatrix_x4(bf[nb],
                            bbase + (uint32_t)(n * 128 + ((kc ^ (n & 7)) << 4)));
            }
            #pragma unroll
            for (int mt = 0; mt < 4; mt++)
                #pragma unroll
                for (int nt = 0; nt < 8; nt++)
                    mma16816(acc[mt][nt], af[mt], bf[nt >> 1] + (nt & 1) * 2);
        }
    }

    #pragma unroll
    for (int mt = 0; mt < 4; mt++) {
        #pragma unroll
        for (int h = 0; h < 2; h++) {
            int r = row0 + wm + mt * 16 + (lane >> 2) + h * 8;
            size_t rowN = (size_t)r * N;
            #pragma unroll
            for (int nt = 0; nt < 8; nt++) {
                int c = col0 + wn + nt * 8 + (lane & 3) * 2;
                float v0 = acc[mt][nt][h * 2 + 0];
                float v1 = acc[mt][nt][h * 2 + 1];
                if (bias) { v0 += bias[c]; v1 += bias[c + 1]; }
                if (res) {
                    float2 r2 = *reinterpret_cast<const float2*>(res + rowN + c);
                    v0 += r2.x; v1 += r2.y;
                }
                if (RELU) { v0 = fmaxf(v0, 0.f); v1 = fmaxf(v1, 0.f); }
                if (W32) {
                    float2 o = make_float2(v0, v1);
                    *reinterpret_cast<float2*>(C32 + rowN + c) = o;
                }
                if (W16) {
                    __half2 hh = __floats2half2_rn(v0, v1);
                    *reinterpret_cast<__half2*>(C16 + rowN + c) = hh;
                }
            }
        }
    }
}

// ---------------------------------------------------------------------------
// LayerNorm: one block per row of 1024; writes fp32 + fp16
// ---------------------------------------------------------------------------
__global__ __launch_bounds__(256) void ln_kernel(
    const float* __restrict__ x, const float* __restrict__ g,
    const float* __restrict__ b, float* __restrict__ outf,
    __half* __restrict__ outh)
{
    int row = blockIdx.x;
    int tid = threadIdx.x;
    const float* xr = x + (size_t)row * kD;

    float4 v = *reinterpret_cast<const float4*>(&xr[tid * 4]);
    float s  = v.x + v.y + v.z + v.w;
    float s2 = v.x * v.x + v.y * v.y + v.z * v.z + v.w * v.w;
    #pragma unroll
    for (int o = 16; o > 0; o >>= 1) {
        s  += __shfl_xor_sync(0xffffffffu, s,  o);
        s2 += __shfl_xor_sync(0xffffffffu, s2, o);
    }
    __shared__ float red[16];
    __shared__ float sh_mean, sh_rstd;
    int w = tid >> 5, l = tid & 31;
    if (l == 0) { red[w] = s; red[8 + w] = s2; }
    __syncthreads();
    if (tid == 0) {
        float S = 0.f, S2 = 0.f;
        #pragma unroll
        for (int i = 0; i < 8; i++) { S += red[i]; S2 += red[8 + i]; }
        float mean = S * (1.0f / kD);
        float var  = S2 * (1.0f / kD) - mean * mean;
        sh_mean = mean;
        sh_rstd = rsqrtf(var + 1e-5f);
    }
    __syncthreads();
    float mean = sh_mean, rstd = sh_rstd;
    float4 gv = *reinterpret_cast<const float4*>(&g[tid * 4]);
    float4 bv = *reinterpret_cast<const float4*>(&b[tid * 4]);
    float4 o4;
    o4.x = (v.x - mean) * rstd * gv.x + bv.x;
    o4.y = (v.y - mean) * rstd * gv.y + bv.y;
    o4.z = (v.z - mean) * rstd * gv.z + bv.z;
    o4.w = (v.w - mean) * rstd * gv.w + bv.w;
    *reinterpret_cast<float4*>(&outf[(size_t)row * kD + tid * 4]) = o4;
    __half2 h0 = __floats2half2_rn(o4.x, o4.y);
    __half2 h1 = __floats2half2_rn(o4.z, o4.w);
    uint2 u = make_uint2(*reinterpret_cast<uint32_t*>(&h0),
                         *reinterpret_cast<uint32_t*>(&h1));
    *reinterpret_cast<uint2*>(&outh[(size_t)row * kD + tid * 4]) = u;
}

// ---------------------------------------------------------------------------
// Weight transpose+convert: wq/wk/wv [H,D,E] f32 -> [N=3072][K=1024] f16
// ---------------------------------------------------------------------------
__global__ __launch_bounds__(256) void wqkv_t_kernel(
    const float* __restrict__ wq, const float* __restrict__ wk,
    const float* __restrict__ wv, __half* __restrict__ out)
{
    __shared__ float tile[32][33];
    int z = blockIdx.z;
    int sec = z >> 4, h = z & 15;
    const float* in = ((sec == 0) ? wq : (sec == 1) ? wk : wv) +
                      (size_t)h * kD * kE;
    int d0 = blockIdx.x * 32, e0 = blockIdx.y * 32;
    int x = threadIdx.x & 31, y0 = threadIdx.x >> 5;   // y0 in 0..7
    #pragma unroll
    for (int j = 0; j < 32; j += 8)
        tile[y0 + j][x] = in[(size_t)(d0 + y0 + j) * kE + e0 + x];
    __syncthreads();
    #pragma unroll
    for (int j = 0; j < 32; j += 8)
        out[(size_t)(sec * kD + h * kE + e0 + y0 + j) * kD + d0 + x] =
            __float2half(tile[x][y0 + j]);
}

// Generic transpose+convert: in [R,C] f32 -> out [C,R] f16
__global__ __launch_bounds__(256) void tr_kernel(
    const float* __restrict__ in, __half* __restrict__ out, int R, int C)
{
    __shared__ float tile[32][33];
    int r0 = blockIdx.y * 32, c0 = blockIdx.x * 32;
    int x = threadIdx.x & 31, y0 = threadIdx.x >> 5;
    #pragma unroll
    for (int j = 0; j < 32; j += 8)
        tile[y0 + j][x] = in[(size_t)(r0 + y0 + j) * C + c0 + x];
    __syncthreads();
    #pragma unroll
    for (int j = 0; j < 32; j += 8)
        out[(size_t)(c0 + y0 + j) * R + r0 + x] = __float2half(tile[x][y0 + j]);
}

// ---------------------------------------------------------------------------
// Causal flash attention, f16 HMMA (FlashAttention-2 register pipeline).
// Block = 128 queries of one (b,h); 8 warps x 16 query rows; key tiles of 64.
// ---------------------------------------------------------------------------
constexpr int ATTN_SMEM = 16384 + 3 * 16384;   // 65536

__global__ __launch_bounds__(256) void attn_mma_kernel(
    const __half* __restrict__ QKV, __half* __restrict__ O)
{
    extern __shared__ char smem[];
    uint32_t sb = smem_u32(smem);
    uint32_t qsm = sb;

    const int qb = blockIdx.x, h = blockIdx.y, b = blockIdx.z;
    const int tid = threadIdx.x;
    const int wid = tid >> 5, lane = tid & 31;
    const int g  = lane >> 2, t4 = lane & 3;
    const int q0 = qb * 128;
    const int nt = 2 * qb + 2;              // key tiles of 64
    const int qrow0 = q0 + wid * 16;

    const __half* base = QKV + (size_t)(b * kT) * kQKVN + h * kE;

    // Q tile: 128 rows x 128B
    #pragma unroll
    for (int j = 0; j < 4; j++) {
        int idx = tid + j * 256;
        int r = idx >> 3, cc = idx & 7;
        uint32_t off = (uint32_t)(r * 128 + ((cc ^ (r & 7)) << 4));
        cp_async16(qsm + off, base + (size_t)(q0 + r) * kQKVN + cc * 8);
    }

    auto load_kv = [&](int j, int s) {
        uint32_t kb = sb + 16384 + (uint32_t)s * 16384u;
        const __half* Kp = base + kD;
        const __half* Vp = base + 2 * kD;
        #pragma unroll
        for (int jj = 0; jj < 2; jj++) {
            int idx = tid + jj * 256;
            int r = idx >> 3, cc = idx & 7;
            uint32_t off = (uint32_t)(r * 128 + ((cc ^ (r & 7)) << 4));
            cp_async16(kb + off,        Kp + (size_t)(j * 64 + r) * kQKVN + cc * 8);
            cp_async16(kb + 8192 + off, Vp + (size_t)(j * 64 + r) * kQKVN + cc * 8);
        }
        asm volatile("cp.async.commit_group;" ::: "memory");
    };

    load_kv(0, 0);
    load_kv(1, 1);

    uint32_t qf[4][4];
    float oacc[8][4];
    #pragma unroll
    for (int t = 0; t < 8; t++)
        #pragma unroll
        for (int q = 0; q < 4; q++) oacc[t][q] = 0.f;
    float m0 = -1e30f, m1 = -1e30f, l0 = 0.f, l1 = 0.f;
    const float scale = 0.125f;

    for (int i = 0; i < nt; i++) {
        if (i < nt - 1) asm volatile("cp.async.wait_group 1;" ::: "memory");
        else            asm volatile("cp.async.wait_group 0;" ::: "memory");
        __syncthreads();

        if (i == 0) {
            #pragma unroll
            for (int kc = 0; kc < 4; kc++) {
                int m  = wid * 16 + (lane & 7) + ((lane >> 3) & 1) * 8;
                int ch = kc * 2 + (lane >> 4);
                ldmatrix_x4(qf[kc],
                            qsm + (uint32_t)(m * 128 + ((ch ^ (m & 7)) << 4)));
            }
        }
        if (i + 2 < nt) load_kv(i + 2, (i + 2) % 3);

        uint32_t kb = sb + 16384 + (uint32_t)(i % 3) * 16384u;
        uint32_t vb = kb + 8192;

        // ---- S = Q K^T ----
        float sacc[8][4];
        #pragma unroll
        for (int t = 0; t < 8; t++)
            #pragma unroll
            for (int q = 0; q < 4; q++) sacc[t][q] = 0.f;

        #pragma unroll
        for (int kc = 0; kc < 4; kc++) {
            #pragma unroll
            for (int np = 0; np < 4; np++) {
                int n  = np * 16 + (lane & 7) + (lane >> 4) * 8;
                int ch = kc * 2 + ((lane >> 3) & 1);
                uint32_t bf[4];
                ldmatrix_x4(bf, kb + (uint32_t)(n * 128 + ((ch ^ (n & 7)) << 4)));
                mma16816(sacc[np * 2 + 0], qf[kc], bf);
                mma16816(sacc[np * 2 + 1], qf[kc], bf + 2);
            }
        }

        // ---- scale + causal mask ----
        const int j0 = i * 64;
        const int gr0 = qrow0 + g, gr1 = gr0 + 8;
        const bool need_mask = (j0 + 63 > qrow0);
        #pragma unroll
        for (int t = 0; t < 8; t++) {
            int gc = j0 + t * 8 + t4 * 2;
            float s0 = sacc[t][0] * scale, s1 = sacc[t][1] * scale;
            float s2 = sacc[t][2] * scale, s3 = sacc[t][3] * scale;
            if (need_mask) {
                if (gc     > gr0) s0 = -1e30f;
                if (gc + 1 > gr0) s1 = -1e30f;
                if (gc     > gr1) s2 = -1e30f;
                if (gc + 1 > gr1) s3 = -1e30f;
            }
            sacc[t][0] = s0; sacc[t][1] = s1; sacc[t][2] = s2; sacc[t][3] = s3;
        }

        // ---- online softmax (quad reduction over lanes t4) ----
        float rmax0 = -1e30f, rmax1 = -1e30f;
        #pragma unroll
        for (int t = 0; t < 8; t++) {
            rmax0 = fmaxf(rmax0, fmaxf(sacc[t][0], sacc[t][1]));
            rmax1 = fmaxf(rmax1, fmaxf(sacc[t][2], sacc[t][3]));
        }
        rmax0 = fmaxf(rmax0, __shfl_xor_sync(0xffffffffu, rmax0, 1));
        rmax0 = fmaxf(rmax0, __shfl_xor_sync(0xffffffffu, rmax0, 2));
        rmax1 = fmaxf(rmax1, __shfl_xor_sync(0xffffffffu, rmax1, 1));
        rmax1 = fmaxf(rmax1, __shfl_xor_sync(0xffffffffu, rmax1, 2));

        float mn0 = fmaxf(m0, rmax0), mn1 = fmaxf(m1, rmax1);
        float f0 = __expf(m0 - mn0),  f1 = __expf(m1 - mn1);
        float sum0 = 0.f, sum1 = 0.f;
        #pragma unroll
        for (int t = 0; t < 8; t++) {
            float p0 = __expf(sacc[t][0] - mn0);
            float p1 = __expf(sacc[t][1] - mn0);
            float p2 = __expf(sacc[t][2] - mn1);
            float p3 = __expf(sacc[t][3] - mn1);
            sacc[t][0] = p0; sacc[t][1] = p1; sacc[t][2] = p2; sacc[t][3] = p3;
            sum0 += p0 + p1; sum1 += p2 + p3;
        }
        sum0 += __shfl_xor_sync(0xffffffffu, sum0, 1);
        sum0 += __shfl_xor_sync(0xffffffffu, sum0, 2);
        sum1 += __shfl_xor_sync(0xffffffffu, sum1, 1);
        sum1 += __shfl_xor_sync(0xffffffffu, sum1, 2);
        l0 = l0 * f0 + sum0; m0 = mn0;
        l1 = l1 * f1 + sum1; m1 = mn1;

        #pragma unroll
        for (int t = 0; t < 8; t++) {
            oacc[t][0] *= f0; oacc[t][1] *= f0;
            oacc[t][2] *= f1; oacc[t][3] *= f1;
        }

        // ---- O += P V ----
        #pragma unroll
        for (int kc = 0; kc < 4; kc++) {
            uint32_t pa[4];
            pa[0] = packh2(sacc[2 * kc][0],     sacc[2 * kc][1]);
            pa[1] = packh2(sacc[2 * kc][2],     sacc[2 * kc][3]);
            pa[2] = packh2(sacc[2 * kc + 1][0], sacc[2 * kc + 1][1]);
            pa[3] = packh2(sacc[2 * kc + 1][2], sacc[2 * kc + 1][3]);
            #pragma unroll
            for (int np = 0; np < 4; np++) {
                int kk = kc * 16 + (lane & 7) + ((lane >> 3) & 1) * 8;  // V row
                int ch = np * 2 + (lane >> 4);                          // E chunk
                uint32_t bf[4];
                ldmatrix_x4_trans(bf,
                    vb + (uint32_t)(kk * 128 + ((ch ^ (kk & 7)) << 4)));
                mma16816(oacc[np * 2 + 0], pa, bf);
                mma16816(oacc[np * 2 + 1], pa, bf + 2);
            }
        }
    }

    // ---- normalize + write ----
    float inv0 = 1.0f / l0, inv1 = 1.0f / l1;
    size_t row0 = (size_t)(b * kT + qrow0 + g) * kD;
    size_t row1 = row0 + (size_t)8 * kD;
    #pragma unroll
    for (int t = 0; t < 8; t++) {
        int col = h * kE + t * 8 + t4 * 2;
        __half2 o0 = __floats2half2_rn(oacc[t][0] * inv0, oacc[t][1] * inv0);
        __half2 o1 = __floats2half2_rn(oacc[t][2] * inv1, oacc[t][3] * inv1);
        *reinterpret_cast<__half2*>(O + row0 + col) = o0;
        *reinterpret_cast<__half2*>(O + row1 + col) = o1;
    }
}

// ---------------------------------------------------------------------------
// Launch
// ---------------------------------------------------------------------------
extern "C" void kernel_launch(void* const* d_in, const int* in_sizes, int n_in,
                              void* d_out, int out_size)
{
    const float* x      = (const float*)d_in[0];
    const float* wq     = (const float*)d_in[1];
    const float* wk     = (const float*)d_in[2];
    const float* wv     = (const float*)d_in[3];
    const float* w_proj = (const float*)d_in[4];
    const float* b_proj = (const float*)d_in[5];
    const float* w1     = (const float*)d_in[6];
    const float* b1     = (const float*)d_in[7];
    const float* w2     = (const float*)d_in[8];
    const float* b2     = (const float*)d_in[9];
    const float* g1     = (const float*)d_in[10];
    const float* be1    = (const float*)d_in[11];
    const float* g2     = (const float*)d_in[12];
    const float* be2    = (const float*)d_in[13];
    float* out = (float*)d_out;

    float  *ln1f, *x2, *ln2f;
    __half *ln1h, *qkvh, *atth, *ln2h, *hidh, *wqkvh, *wph, *w1t, *w2t;
    cudaGetSymbolAddress((void**)&ln1f,  g_ln1f);
    cudaGetSymbolAddress((void**)&ln1h,  g_ln1h);
    cudaGetSymbolAddress((void**)&qkvh,  g_qkvh);
    cudaGetSymbolAddress((void**)&atth,  g_atth);
    cudaGetSymbolAddress((void**)&x2,    g_x2);
    cudaGetSymbolAddress((void**)&ln2f,  g_ln2f);
    cudaGetSymbolAddress((void**)&ln2h,  g_ln2h);
    cudaGetSymbolAddress((void**)&hidh,  g_hidh);
    cudaGetSymbolAddress((void**)&wqkvh, g_wqkv);
    cudaGetSymbolAddress((void**)&wph,   g_wp);
    cudaGetSymbolAddress((void**)&w1t,   g_w1t);
    cudaGetSymbolAddress((void**)&w2t,   g_w2t);

    cudaFuncSetAttribute(attn_mma_kernel,
                         cudaFuncAttributeMaxDynamicSharedMemorySize, ATTN_SMEM);
    cudaFuncSetAttribute(gemm_mma<0, 1, 0>,
                         cudaFuncAttributeMaxDynamicSharedMemorySize, GEMM_SMEM);
    cudaFuncSetAttribute(gemm_mma<0, 0, 1>,
                         cudaFuncAttributeMaxDynamicSharedMemorySize, GEMM_SMEM);
    cudaFuncSetAttribute(gemm_mma<1, 0, 1>,
                         cudaFuncAttributeMaxDynamicSharedMemorySize, GEMM_SMEM);

    // 1) LN1 (f32 residual + f16 GEMM input)
    ln_kernel<<<kM, 256>>>(x, g1, be1, ln1f, ln1h);

    // 2) Weight transposes + f16 conversion
    wqkv_t_kernel<<<dim3(kD / 32, kE / 32, 48), 256>>>(wq, wk, wv, wqkvh);
    tr_kernel<<<dim3(kD / 32, kD / 32), 256>>>(w_proj, wph, kD, kD);
    tr_kernel<<<dim3(kF / 32, kD / 32), 256>>>(w1, w1t, kD, kF);
    tr_kernel<<<dim3(kD / 32, kF / 32), 256>>>(w2, w2t, kF, kD);

    // 3) QKV GEMM: [8192,1024] @ [3072,1024]^T -> f16
    gemm_mma<0, 0, 1><<<dim3(kQKVN / 128, kM / 128), 128, GEMM_SMEM>>>(
        ln1h, wqkvh, nullptr, nullptr, nullptr, qkvh, kM, kQKVN, kD);

    // 4) Causal flash attention (f16 HMMA) -> f16
    attn_mma_kernel<<<dim3(kT / 128, kH, kB), 256, ATTN_SMEM>>>(qkvh, atth);

    // 5) Output projection + bias + residual(ln1) -> x2 (f32)
    gemm_mma<0, 1, 0><<<dim3(kD / 128, kM / 128), 128, GEMM_SMEM>>>(
        atth, wph, b_proj, ln1f, x2, nullptr, kM, kD, kD);

    // 6) LN2
    ln_kernel<<<kM, 256>>>(x2, g2, be2, ln2f, ln2h);

    // 7) FFN1 + ReLU -> f16 hidden
    gemm_mma<1, 0, 1><<<dim3(kF / 128, kM / 128), 128, GEMM_SMEM>>>(
        ln2h, w1t, b1, nullptr, nullptr, hidh, kM, kF, kD);

    // 8) FFN2 + bias + residual(ln2) -> output (f32)
    gemm_mma<0, 1, 0><<<dim3(kD / 128, kM / 128), 128, GEMM_SMEM>>>(
        hidh, w2t, b2, ln2f, out, nullptr, kM, kD, kF);
}

// round 11
// speedup vs baseline: 1.4638x; 1.4638x over previous
#include <cuda_runtime.h>
#include <cuda_fp16.h>
#include <cstdint>

// ---------------------------------------------------------------------------
// Problem constants
// ---------------------------------------------------------------------------
constexpr int kB = 8;
constexpr int kT = 1024;
constexpr int kD = 1024;          // n_embd
constexpr int kH = 16;            // heads
constexpr int kE = 64;            // head size
constexpr int kF = 4096;          // ffn hidden
constexpr int kM = kB * kT;       // 8192 rows
constexpr int kQKVN = 3 * kD;     // 3072

// ---------------------------------------------------------------------------
// Scratch (device globals: allocation-free per harness rules)
// ---------------------------------------------------------------------------
__device__ __align__(16) float  g_ln1f[(size_t)kM * kD];
__device__ __align__(16) __half g_ln1h[(size_t)kM * kD];
__device__ __align__(16) __half g_qkvh[(size_t)kM * kQKVN];
__device__ __align__(16) __half g_atth[(size_t)kM * kD];
__device__ __align__(16) float  g_x2  [(size_t)kM * kD];
__device__ __align__(16) float  g_ln2f[(size_t)kM * kD];
__device__ __align__(16) __half g_ln2h[(size_t)kM * kD];
__device__ __align__(16) __half g_hidh[(size_t)kM * kF];
__device__ __align__(16) __half g_wqkv[(size_t)kQKVN * kD];   // [N=3072][K=1024]
__device__ __align__(16) __half g_wp  [(size_t)kD * kD];      // [N=1024][K=1024]
__device__ __align__(16) __half g_w1t [(size_t)kF * kD];      // [N=4096][K=1024]
__device__ __align__(16) __half g_w2t [(size_t)kD * kF];      // [N=1024][K=4096]

// ---------------------------------------------------------------------------
// Low-level helpers
// ---------------------------------------------------------------------------
__device__ __forceinline__ uint32_t smem_u32(const void* p) {
    uint32_t r;
    asm("{ .reg .u64 t; cvta.to.shared.u64 t, %1; cvt.u32.u64 %0, t; }"
        : "=r"(r) : "l"(p));
    return r;
}

__device__ __forceinline__ void cp_async16(uint32_t dst, const void* src) {
    asm volatile("cp.async.cg.shared.global [%0], [%1], 16;"
                 :: "r"(dst), "l"(src));
}

__device__ __forceinline__ void ldmatrix_x4(uint32_t* r, uint32_t addr) {
    asm volatile("ldmatrix.sync.aligned.m8n8.x4.shared.b16 {%0,%1,%2,%3}, [%4];"
                 : "=r"(r[0]), "=r"(r[1]), "=r"(r[2]), "=r"(r[3]) : "r"(addr));
}

__device__ __forceinline__ void ldmatrix_x4_trans(uint32_t* r, uint32_t addr) {
    asm volatile("ldmatrix.sync.aligned.m8n8.x4.trans.shared.b16 {%0,%1,%2,%3}, [%4];"
                 : "=r"(r[0]), "=r"(r[1]), "=r"(r[2]), "=r"(r[3]) : "r"(addr));
}

__device__ __forceinline__ void mma16816(float* d,
                                         const uint32_t* a, const uint32_t* b) {
    asm volatile(
        "mma.sync.aligned.m16n8k16.row.col.f32.f16.f16.f32 "
        "{%0,%1,%2,%3}, {%4,%5,%6,%7}, {%8,%9}, {%0,%1,%2,%3};"
        : "+f"(d[0]), "+f"(d[1]), "+f"(d[2]), "+f"(d[3])
        : "r"(a[0]), "r"(a[1]), "r"(a[2]), "r"(a[3]), "r"(b[0]), "r"(b[1]));
}

__device__ __forceinline__ uint32_t packh2(float a, float b) {
    __half2 h = __floats2half2_rn(a, b);
    return *reinterpret_cast<uint32_t*>(&h);
}

// ---------------------------------------------------------------------------
// HMMA GEMM: C[M,N] = A_h[M,K] @ B_h[N,K]^T  (+bias) (+res) (relu)
// 128x128 block tile, BK=64, 3-stage cp.async pipeline, 256 threads (8 warps,
// 64x32 warp tiles, 2 CTAs/SM -> 16 warps/SM). Smem: 128 rows x 128B,
// XOR-swizzled.  [Proven round-9 configuration.]
// ---------------------------------------------------------------------------
constexpr int GEMM_SMEM = 3 * 32768;   // 96 KB

template <int RELU, int W32, int W16>
__global__ __launch_bounds__(256)
void gemm_mma(const __half* __restrict__ A, const __half* __restrict__ B,
              const float* __restrict__ bias, const float* __restrict__ res,
              float* __restrict__ C32, __half* __restrict__ C16,
              int M, int N, int K)
{
    extern __shared__ char smem[];
    uint32_t sb = smem_u32(smem);

    const int tid  = threadIdx.x;
    const int wid  = tid >> 5;
    const int lane = tid & 31;
    const int wm = (wid & 1) * 64;        // warp row offset in tile
    const int wn = (wid >> 1) * 32;       // warp col offset in tile
    const int row0 = blockIdx.y * 128;
    const int col0 = blockIdx.x * 128;
    const __half* Ab = A + (size_t)row0 * K;
    const __half* Bb = B + (size_t)col0 * K;
    const int nch = K >> 6;               // chunks of K=64

    auto load_chunk = [&](int c, int s) {
        uint32_t base = sb + (uint32_t)s * 32768u;
        const __half* Ap = Ab + c * 64;
        const __half* Bp = Bb + c * 64;
        #pragma unroll
        for (int j = 0; j < 4; j++) {
            int idx = tid + j * 256;              // 0..1023
            int r  = idx >> 3;
            int cc = idx & 7;
            uint32_t off = (uint32_t)(r * 128 + ((cc ^ (r & 7)) << 4));
            cp_async16(base + off,         Ap + (size_t)r * K + cc * 8);
            cp_async16(base + 16384 + off, Bp + (size_t)r * K + cc * 8);
        }
        asm volatile("cp.async.commit_group;" ::: "memory");
    };

    float acc[4][4][4];
    #pragma unroll
    for (int i = 0; i < 4; i++)
        #pragma unroll
        for (int j = 0; j < 4; j++)
            #pragma unroll
            for (int q = 0; q < 4; q++) acc[i][j][q] = 0.f;

    load_chunk(0, 0);
    load_chunk(1, 1);

    for (int i = 0; i < nch; i++) {
        if (i < nch - 1) asm volatile("cp.async.wait_group 1;" ::: "memory");
        else             asm volatile("cp.async.wait_group 0;" ::: "memory");
        __syncthreads();

        if (i + 2 < nch) load_chunk(i + 2, (i + 2) % 3);

        uint32_t abase = sb + (uint32_t)(i % 3) * 32768u;
        uint32_t bbase = abase + 16384;

        #pragma unroll
        for (int kk = 0; kk < 4; kk++) {          // 4 k-steps of 16
            uint32_t af[4][4];
            #pragma unroll
            for (int mt = 0; mt < 4; mt++) {
                int m  = wm + mt * 16 + (lane & 7) + ((lane >> 3) & 1) * 8;
                int kc = kk * 2 + (lane >> 4);
                ldmatrix_x4(af[mt],
                            abase + (uint32_t)(m * 128 + ((kc ^ (m & 7)) << 4)));
            }
            uint32_t bf[2][4];
            #pragma unroll
            for (int nb = 0; nb < 2; nb++) {
                int n  = wn + nb * 16 + (lane & 7) + (lane >> 4) * 8;
                int kc = kk * 2 + ((lane >> 3) & 1);
                ldmatrix_x4(bf[nb],
                            bbase + (uint32_t)(n * 128 + ((kc ^ (n & 7)) << 4)));
            }
            #pragma unroll
            for (int mt = 0; mt < 4; mt++)
                #pragma unroll
                for (int nt = 0; nt < 4; nt++)
                    mma16816(acc[mt][nt], af[mt], bf[nt >> 1] + (nt & 1) * 2);
        }
    }

    #pragma unroll
    for (int mt = 0; mt < 4; mt++) {
        #pragma unroll
        for (int h = 0; h < 2; h++) {
            int r = row0 + wm + mt * 16 + (lane >> 2) + h * 8;
            size_t rowN = (size_t)r * N;
            #pragma unroll
            for (int nt = 0; nt < 4; nt++) {
                int c = col0 + wn + nt * 8 + (lane & 3) * 2;
                float v0 = acc[mt][nt][h * 2 + 0];
                float v1 = acc[mt][nt][h * 2 + 1];
                if (bias) { v0 += bias[c]; v1 += bias[c + 1]; }
                if (res) {
                    float2 r2 = *reinterpret_cast<const float2*>(res + rowN + c);
                    v0 += r2.x; v1 += r2.y;
                }
                if (RELU) { v0 = fmaxf(v0, 0.f); v1 = fmaxf(v1, 0.f); }
                if (W32) {
                    float2 o = make_float2(v0, v1);
                    *reinterpret_cast<float2*>(C32 + rowN + c) = o;
                }
                if (W16) {
                    __half2 hh = __floats2half2_rn(v0, v1);
                    *reinterpret_cast<__half2*>(C16 + rowN + c) = hh;
                }
            }
        }
    }
}

// ---------------------------------------------------------------------------
// LayerNorm: one block per row of 1024; writes fp32 + fp16
// ---------------------------------------------------------------------------
__global__ __launch_bounds__(256) void ln_kernel(
    const float* __restrict__ x, const float* __restrict__ g,
    const float* __restrict__ b, float* __restrict__ outf,
    __half* __restrict__ outh)
{
    int row = blockIdx.x;
    int tid = threadIdx.x;
    const float* xr = x + (size_t)row * kD;

    float4 v = *reinterpret_cast<const float4*>(&xr[tid * 4]);
    float s  = v.x + v.y + v.z + v.w;
    float s2 = v.x * v.x + v.y * v.y + v.z * v.z + v.w * v.w;
    #pragma unroll
    for (int o = 16; o > 0; o >>= 1) {
        s  += __shfl_xor_sync(0xffffffffu, s,  o);
        s2 += __shfl_xor_sync(0xffffffffu, s2, o);
    }
    __shared__ float red[16];
    __shared__ float sh_mean, sh_rstd;
    int w = tid >> 5, l = tid & 31;
    if (l == 0) { red[w] = s; red[8 + w] = s2; }
    __syncthreads();
    if (tid == 0) {
        float S = 0.f, S2 = 0.f;
        #pragma unroll
        for (int i = 0; i < 8; i++) { S += red[i]; S2 += red[8 + i]; }
        float mean = S * (1.0f / kD);
        float var  = S2 * (1.0f / kD) - mean * mean;
        sh_mean = mean;
        sh_rstd = rsqrtf(var + 1e-5f);
    }
    __syncthreads();
    float mean = sh_mean, rstd = sh_rstd;
    float4 gv = *reinterpret_cast<const float4*>(&g[tid * 4]);
    float4 bv = *reinterpret_cast<const float4*>(&b[tid * 4]);
    float4 o4;
    o4.x = (v.x - mean) * rstd * gv.x + bv.x;
    o4.y = (v.y - mean) * rstd * gv.y + bv.y;
    o4.z = (v.z - mean) * rstd * gv.z + bv.z;
    o4.w = (v.w - mean) * rstd * gv.w + bv.w;
    *reinterpret_cast<float4*>(&outf[(size_t)row * kD + tid * 4]) = o4;
    __half2 h0 = __floats2half2_rn(o4.x, o4.y);
    __half2 h1 = __floats2half2_rn(o4.z, o4.w);
    uint2 u = make_uint2(*reinterpret_cast<uint32_t*>(&h0),
                         *reinterpret_cast<uint32_t*>(&h1));
    *reinterpret_cast<uint2*>(&outh[(size_t)row * kD + tid * 4]) = u;
}

// ---------------------------------------------------------------------------
// Unified weight transpose+convert (single launch for all 4 weight tensors).
// Tile blocks: [0,3072) wqkv, [3072,4096) w_proj, [4096,8192) w1,
// [8192,12288) w2. Each block transposes one 32x32 f32 tile -> f16.
// ---------------------------------------------------------------------------
constexpr int TRQKV = 3072;
constexpr int TRWP  = 1024;
constexpr int TRW1  = 4096;
constexpr int TRW2  = 4096;
constexpr int TR_TOTAL = TRQKV + TRWP + TRW1 + TRW2;   // 12288

__global__ __launch_bounds__(256) void trans_all_kernel(
    const float* __restrict__ wq, const float* __restrict__ wk,
    const float* __restrict__ wv, const float* __restrict__ wp,
    const float* __restrict__ w1, const float* __restrict__ w2,
    __half* __restrict__ owqkv, __half* __restrict__ owp,
    __half* __restrict__ ow1,   __half* __restrict__ ow2)
{
    __shared__ float tile[32][33];
    int t = blockIdx.x;
    const float* in;
    __half* out;
    int R, C, r0, c0;
    bool qkv = false;
    int sec = 0, h = 0;

    if (t < TRQKV) {
        qkv = true;
        int sh = t >> 6;                 // (sec,h) pair, 64 tiles each
        int tt = t & 63;
        sec = sh >> 4; h = sh & 15;
        in = ((sec == 0) ? wq : (sec == 1) ? wk : wv) + (size_t)h * kD * kE;
        R = kD; C = kE;
        r0 = (tt >> 1) * 32;             // d
        c0 = (tt & 1) * 32;              // e
        out = owqkv;
    } else if (t < TRQKV + TRWP) {
        t -= TRQKV; in = wp; out = owp; R = kD; C = kD;
        r0 = (t >> 5) * 32; c0 = (t & 31) * 32;
    } else if (t < TRQKV + TRWP + TRW1) {
        t -= TRQKV + TRWP; in = w1; out = ow1; R = kD; C = kF;
        r0 = (t >> 7) * 32; c0 = (t & 127) * 32;
    } else {
        t -= TRQKV + TRWP + TRW1; in = w2; out = ow2; R = kF; C = kD;
        r0 = (t >> 5) * 32; c0 = (t & 31) * 32;
    }

    int x = threadIdx.x & 31, y0 = threadIdx.x >> 5;
    #pragma unroll
    for (int j = 0; j < 32; j += 8)
        tile[y0 + j][x] = in[(size_t)(r0 + y0 + j) * C + c0 + x];
    __syncthreads();
    if (qkv) {
        #pragma unroll
        for (int j = 0; j < 32; j += 8)
            out[(size_t)(sec * kD + h * kE + c0 + y0 + j) * kD + r0 + x] =
                __float2half(tile[x][y0 + j]);
    } else {
        #pragma unroll
        for (int j = 0; j < 32; j += 8)
            out[(size_t)(c0 + y0 + j) * R + r0 + x] =
                __float2half(tile[x][y0 + j]);
    }
}

// ---------------------------------------------------------------------------
// Causal flash attention, f16 HMMA (FlashAttention-2 register pipeline).
// Block = 128 queries of one (b,h); 8 warps x 16 query rows; key tiles of 64.
// qb reversed vs blockIdx so the longest (most key tiles) CTAs launch first.
// ---------------------------------------------------------------------------
constexpr int ATTN_SMEM = 16384 + 3 * 16384;   // 65536

__global__ __launch_bounds__(256) void attn_mma_kernel(
    const __half* __restrict__ QKV, __half* __restrict__ O)
{
    extern __shared__ char smem[];
    uint32_t sb = smem_u32(smem);
    uint32_t qsm = sb;

    const int qb = (int)gridDim.x - 1 - (int)blockIdx.x;   // long blocks first
    const int h = blockIdx.y, b = blockIdx.z;
    const int tid = threadIdx.x;
    const int wid = tid >> 5, lane = tid & 31;
    const int g  = lane >> 2, t4 = lane & 3;
    const int q0 = qb * 128;
    const int nt = 2 * qb + 2;              // key tiles of 64
    const int qrow0 = q0 + wid * 16;

    const __half* base = QKV + (size_t)(b * kT) * kQKVN + h * kE;

    // Q tile: 128 rows x 128B
    #pragma unroll
    for (int j = 0; j < 4; j++) {
        int idx = tid + j * 256;
        int r = idx >> 3, cc = idx & 7;
        uint32_t off = (uint32_t)(r * 128 + ((cc ^ (r & 7)) << 4));
        cp_async16(qsm + off, base + (size_t)(q0 + r) * kQKVN + cc * 8);
    }

    auto load_kv = [&](int j, int s) {
        uint32_t kb = sb + 16384 + (uint32_t)s * 16384u;
        const __half* Kp = base + kD;
        const __half* Vp = base + 2 * kD;
        #pragma unroll
        for (int jj = 0; jj < 2; jj++) {
            int idx = tid + jj * 256;
            int r = idx >> 3, cc = idx & 7;
            uint32_t off = (uint32_t)(r * 128 + ((cc ^ (r & 7)) << 4));
            cp_async16(kb + off,        Kp + (size_t)(j * 64 + r) * kQKVN + cc * 8);
            cp_async16(kb + 8192 + off, Vp + (size_t)(j * 64 + r) * kQKVN + cc * 8);
        }
        asm volatile("cp.async.commit_group;" ::: "memory");
    };

    load_kv(0, 0);
    load_kv(1, 1);

    uint32_t qf[4][4];
    float oacc[8][4];
    #pragma unroll
    for (int t = 0; t < 8; t++)
        #pragma unroll
        for (int q = 0; q < 4; q++) oacc[t][q] = 0.f;
    float m0 = -1e30f, m1 = -1e30f, l0 = 0.f, l1 = 0.f;
    const float scale = 0.125f;

    for (int i = 0; i < nt; i++) {
        if (i < nt - 1) asm volatile("cp.async.wait_group 1;" ::: "memory");
        else            asm volatile("cp.async.wait_group 0;" ::: "memory");
        __syncthreads();

        if (i == 0) {
            #pragma unroll
            for (int kc = 0; kc < 4; kc++) {
                int m  = wid * 16 + (lane & 7) + ((lane >> 3) & 1) * 8;
                int ch = kc * 2 + (lane >> 4);
                ldmatrix_x4(qf[kc],
                            qsm + (uint32_t)(m * 128 + ((ch ^ (m & 7)) << 4)));
            }
        }
        if (i + 2 < nt) load_kv(i + 2, (i + 2) % 3);

        uint32_t kb = sb + 16384 + (uint32_t)(i % 3) * 16384u;
        uint32_t vb = kb + 8192;

        // ---- S = Q K^T ----
        float sacc[8][4];
        #pragma unroll
        for (int t = 0; t < 8; t++)
            #pragma unroll
            for (int q = 0; q < 4; q++) sacc[t][q] = 0.f;

        #pragma unroll
        for (int kc = 0; kc < 4; kc++) {
            #pragma unroll
            for (int np = 0; np < 4; np++) {
                int n  = np * 16 + (lane & 7) + (lane >> 4) * 8;
                int ch = kc * 2 + ((lane >> 3) & 1);
                uint32_t bf[4];
                ldmatrix_x4(bf, kb + (uint32_t)(n * 128 + ((ch ^ (n & 7)) << 4)));
                mma16816(sacc[np * 2 + 0], qf[kc], bf);
                mma16816(sacc[np * 2 + 1], qf[kc], bf + 2);
            }
        }

        // ---- scale + causal mask ----
        const int j0 = i * 64;
        const int gr0 = qrow0 + g, gr1 = gr0 + 8;
        const bool need_mask = (j0 + 63 > qrow0);
        #pragma unroll
        for (int t = 0; t < 8; t++) {
            int gc = j0 + t * 8 + t4 * 2;
            float s0 = sacc[t][0] * scale, s1 = sacc[t][1] * scale;
            float s2 = sacc[t][2] * scale, s3 = sacc[t][3] * scale;
            if (need_mask) {
                if (gc     > gr0) s0 = -1e30f;
                if (gc + 1 > gr0) s1 = -1e30f;
                if (gc     > gr1) s2 = -1e30f;
                if (gc + 1 > gr1) s3 = -1e30f;
            }
            sacc[t][0] = s0; sacc[t][1] = s1; sacc[t][2] = s2; sacc[t][3] = s3;
        }

        // ---- online softmax (quad reduction over lanes t4) ----
        float rmax0 = -1e30f, rmax1 = -1e30f;
        #pragma unroll
        for (int t = 0; t < 8; t++) {
            rmax0 = fmaxf(rmax0, fmaxf(sacc[t][0], sacc[t][1]));
            rmax1 = fmaxf(rmax1, fmaxf(sacc[t][2], sacc[t][3]));
        }
        rmax0 = fmaxf(rmax0, __shfl_xor_sync(0xffffffffu, rmax0, 1));
        rmax0 = fmaxf(rmax0, __shfl_xor_sync(0xffffffffu, rmax0, 2));
        rmax1 = fmaxf(rmax1, __shfl_xor_sync(0xffffffffu, rmax1, 1));
        rmax1 = fmaxf(rmax1, __shfl_xor_sync(0xffffffffu, rmax1, 2));

        float mn0 = fmaxf(m0, rmax0), mn1 = fmaxf(m1, rmax1);
        float f0 = __expf(m0 - mn0),  f1 = __expf(m1 - mn1);
        float sum0 = 0.f, sum1 = 0.f;
        #pragma unroll
        for (int t = 0; t < 8; t++) {
            float p0 = __expf(sacc[t][0] - mn0);
            float p1 = __expf(sacc[t][1] - mn0);
            float p2 = __expf(sacc[t][2] - mn1);
            float p3 = __expf(sacc[t][3] - mn1);
            sacc[t][0] = p0; sacc[t][1] = p1; sacc[t][2] = p2; sacc[t][3] = p3;
            sum0 += p0 + p1; sum1 += p2 + p3;
        }
        sum0 += __shfl_xor_sync(0xffffffffu, sum0, 1);
        sum0 += __shfl_xor_sync(0xffffffffu, sum0, 2);
        sum1 += __shfl_xor_sync(0xffffffffu, sum1, 1);
        sum1 += __shfl_xor_sync(0xffffffffu, sum1, 2);
        l0 = l0 * f0 + sum0; m0 = mn0;
        l1 = l1 * f1 + sum1; m1 = mn1;

        #pragma unroll
        for (int t = 0; t < 8; t++) {
            oacc[t][0] *= f0; oacc[t][1] *= f0;
            oacc[t][2] *= f1; oacc[t][3] *= f1;
        }

        // ---- O += P V ----
        #pragma unroll
        for (int kc = 0; kc < 4; kc++) {
            uint32_t pa[4];
            pa[0] = packh2(sacc[2 * kc][0],     sacc[2 * kc][1]);
            pa[1] = packh2(sacc[2 * kc][2],     sacc[2 * kc][3]);
            pa[2] = packh2(sacc[2 * kc + 1][0], sacc[2 * kc + 1][1]);
            pa[3] = packh2(sacc[2 * kc + 1][2], sacc[2 * kc + 1][3]);
            #pragma unroll
            for (int np = 0; np < 4; np++) {
                int kk = kc * 16 + (lane & 7) + ((lane >> 3) & 1) * 8;  // V row
                int ch = np * 2 + (lane >> 4);                          // E chunk
                uint32_t bf[4];
                ldmatrix_x4_trans(bf,
                    vb + (uint32_t)(kk * 128 + ((ch ^ (kk & 7)) << 4)));
                mma16816(oacc[np * 2 + 0], pa, bf);
                mma16816(oacc[np * 2 + 1], pa, bf + 2);
            }
        }
    }

    // ---- normalize + write ----
    float inv0 = 1.0f / l0, inv1 = 1.0f / l1;
    size_t row0 = (size_t)(b * kT + qrow0 + g) * kD;
    size_t row1 = row0 + (size_t)8 * kD;
    #pragma unroll
    for (int t = 0; t < 8; t++) {
        int col = h * kE + t * 8 + t4 * 2;
        __half2 o0 = __floats2half2_rn(oacc[t][0] * inv0, oacc[t][1] * inv0);
        __half2 o1 = __floats2half2_rn(oacc[t][2] * inv1, oacc[t][3] * inv1);
        *reinterpret_cast<__half2*>(O + row0 + col) = o0;
        *reinterpret_cast<__half2*>(O + row1 + col) = o1;
    }
}

// ---------------------------------------------------------------------------
// Launch
// ---------------------------------------------------------------------------
extern "C" void kernel_launch(void* const* d_in, const int* in_sizes, int n_in,
                              void* d_out, int out_size)
{
    const float* x      = (const float*)d_in[0];
    const float* wq     = (const float*)d_in[1];
    const float* wk     = (const float*)d_in[2];
    const float* wv     = (const float*)d_in[3];
    const float* w_proj = (const float*)d_in[4];
    const float* b_proj = (const float*)d_in[5];
    const float* w1     = (const float*)d_in[6];
    const float* b1     = (const float*)d_in[7];
    const float* w2     = (const float*)d_in[8];
    const float* b2     = (const float*)d_in[9];
    const float* g1     = (const float*)d_in[10];
    const float* be1    = (const float*)d_in[11];
    const float* g2     = (const float*)d_in[12];
    const float* be2    = (const float*)d_in[13];
    float* out = (float*)d_out;

    float  *ln1f, *x2, *ln2f;
    __half *ln1h, *qkvh, *atth, *ln2h, *hidh, *wqkvh, *wph, *w1t, *w2t;
    cudaGetSymbolAddress((void**)&ln1f,  g_ln1f);
    cudaGetSymbolAddress((void**)&ln1h,  g_ln1h);
    cudaGetSymbolAddress((void**)&qkvh,  g_qkvh);
    cudaGetSymbolAddress((void**)&atth,  g_atth);
    cudaGetSymbolAddress((void**)&x2,    g_x2);
    cudaGetSymbolAddress((void**)&ln2f,  g_ln2f);
    cudaGetSymbolAddress((void**)&ln2h,  g_ln2h);
    cudaGetSymbolAddress((void**)&hidh,  g_hidh);
    cudaGetSymbolAddress((void**)&wqkvh, g_wqkv);
    cudaGetSymbolAddress((void**)&wph,   g_wp);
    cudaGetSymbolAddress((void**)&w1t,   g_w1t);
    cudaGetSymbolAddress((void**)&w2t,   g_w2t);

    cudaFuncSetAttribute(attn_mma_kernel,
                         cudaFuncAttributeMaxDynamicSharedMemorySize, ATTN_SMEM);
    cudaFuncSetAttribute(gemm_mma<0, 1, 0>,
                         cudaFuncAttributeMaxDynamicSharedMemorySize, GEMM_SMEM);
    cudaFuncSetAttribute(gemm_mma<0, 0, 1>,
                         cudaFuncAttributeMaxDynamicSharedMemorySize, GEMM_SMEM);
    cudaFuncSetAttribute(gemm_mma<1, 0, 1>,
                         cudaFuncAttributeMaxDynamicSharedMemorySize, GEMM_SMEM);

    // 1) LN1 (f32 residual + f16 GEMM input)
    ln_kernel<<<kM, 256>>>(x, g1, be1, ln1f, ln1h);

    // 2) All weight transposes + f16 conversion in ONE launch
    trans_all_kernel<<<TR_TOTAL, 256>>>(wq, wk, wv, w_proj, w1, w2,
                                        wqkvh, wph, w1t, w2t);

    // 3) QKV GEMM: [8192,1024] @ [3072,1024]^T -> f16
    gemm_mma<0, 0, 1><<<dim3(kQKVN / 128, kM / 128), 256, GEMM_SMEM>>>(
        ln1h, wqkvh, nullptr, nullptr, nullptr, qkvh, kM, kQKVN, kD);

    // 4) Causal flash attention (f16 HMMA) -> f16
    attn_mma_kernel<<<dim3(kT / 128, kH, kB), 256, ATTN_SMEM>>>(qkvh, atth);

    // 5) Output projection + bias + residual(ln1) -> x2 (f32)
    gemm_mma<0, 1, 0><<<dim3(kD / 128, kM / 128), 256, GEMM_SMEM>>>(
        atth, wph, b_proj, ln1f, x2, nullptr, kM, kD, kD);

    // 6) LN2
    ln_kernel<<<kM, 256>>>(x2, g2, be2, ln2f, ln2h);

    // 7) FFN1 + ReLU -> f16 hidden
    gemm_mma<1, 0, 1><<<dim3(kF / 128, kM / 128), 256, GEMM_SMEM>>>(
        ln2h, w1t, b1, nullptr, nullptr, hidh, kM, kF, kD);

    // 8) FFN2 + bias + residual(ln2) -> output (f32)
    gemm_mma<0, 1, 0><<<dim3(kD / 128, kM / 128), 256, GEMM_SMEM>>>(
        hidh, w2t, b2, ln2f, out, nullptr, kM, kD, kF);
}

// round 12
// speedup vs baseline: 1.4913x; 1.0188x over previous
#include <cuda_runtime.h>
#include <cuda_fp16.h>
#include <cstdint>

// ---------------------------------------------------------------------------
// Problem constants
// ---------------------------------------------------------------------------
constexpr int kB = 8;
constexpr int kT = 1024;
constexpr int kD = 1024;          // n_embd
constexpr int kH = 16;            // heads
constexpr int kE = 64;            // head size
constexpr int kF = 4096;          // ffn hidden
constexpr int kM = kB * kT;       // 8192 rows
constexpr int kQKVN = 3 * kD;     // 3072

// ---------------------------------------------------------------------------
// Scratch (device globals: allocation-free per harness rules)
// ---------------------------------------------------------------------------
__device__ __align__(16) float  g_ln1f[(size_t)kM * kD];
__device__ __align__(16) __half g_ln1h[(size_t)kM * kD];
__device__ __align__(16) __half g_qkvh[(size_t)kM * kQKVN];
__device__ __align__(16) __half g_atth[(size_t)kM * kD];
__device__ __align__(16) float  g_x2  [(size_t)kM * kD];
__device__ __align__(16) float  g_ln2f[(size_t)kM * kD];
__device__ __align__(16) __half g_ln2h[(size_t)kM * kD];
__device__ __align__(16) __half g_hidh[(size_t)kM * kF];
__device__ __align__(16) __half g_wqkv[(size_t)kQKVN * kD];   // [N=3072][K=1024]
__device__ __align__(16) __half g_wp  [(size_t)kD * kD];      // [N=1024][K=1024]
__device__ __align__(16) __half g_w1t [(size_t)kF * kD];      // [N=4096][K=1024]
__device__ __align__(16) __half g_w2t [(size_t)kD * kF];      // [N=1024][K=4096]

// ---------------------------------------------------------------------------
// Low-level helpers
// ---------------------------------------------------------------------------
__device__ __forceinline__ uint32_t smem_u32(const void* p) {
    uint32_t r;
    asm("{ .reg .u64 t; cvta.to.shared.u64 t, %1; cvt.u32.u64 %0, t; }"
        : "=r"(r) : "l"(p));
    return r;
}

__device__ __forceinline__ void cp_async16(uint32_t dst, const void* src) {
    asm volatile("cp.async.cg.shared.global [%0], [%1], 16;"
                 :: "r"(dst), "l"(src));
}

__device__ __forceinline__ void ldmatrix_x4(uint32_t* r, uint32_t addr) {
    asm volatile("ldmatrix.sync.aligned.m8n8.x4.shared.b16 {%0,%1,%2,%3}, [%4];"
                 : "=r"(r[0]), "=r"(r[1]), "=r"(r[2]), "=r"(r[3]) : "r"(addr));
}

__device__ __forceinline__ void ldmatrix_x4_trans(uint32_t* r, uint32_t addr) {
    asm volatile("ldmatrix.sync.aligned.m8n8.x4.trans.shared.b16 {%0,%1,%2,%3}, [%4];"
                 : "=r"(r[0]), "=r"(r[1]), "=r"(r[2]), "=r"(r[3]) : "r"(addr));
}

__device__ __forceinline__ void mma16816(float* d,
                                         const uint32_t* a, const uint32_t* b) {
    asm volatile(
        "mma.sync.aligned.m16n8k16.row.col.f32.f16.f16.f32 "
        "{%0,%1,%2,%3}, {%4,%5,%6,%7}, {%8,%9}, {%0,%1,%2,%3};"
        : "+f"(d[0]), "+f"(d[1]), "+f"(d[2]), "+f"(d[3])
        : "r"(a[0]), "r"(a[1]), "r"(a[2]), "r"(a[3]), "r"(b[0]), "r"(b[1]));
}

__device__ __forceinline__ uint32_t packh2(float a, float b) {
    __half2 h = __floats2half2_rn(a, b);
    return *reinterpret_cast<uint32_t*>(&h);
}

__device__ __forceinline__ float ex2(float x) {
    float y;
    asm("ex2.approx.ftz.f32 %0, %1;" : "=f"(y) : "f"(x));
    return y;
}

// ---------------------------------------------------------------------------
// HMMA GEMM: C[M,N] = A_h[M,K] @ B_h[N,K]^T  (+bias) (+res) (relu)
// 128x128 block tile, BK=64, 3-stage cp.async pipeline, 256 threads (8 warps,
// 64x32 warp tiles, 2 CTAs/SM -> 16 warps/SM). Smem: 128 rows x 128B,
// XOR-swizzled.  [Proven round-9 configuration — unchanged.]
// ---------------------------------------------------------------------------
constexpr int GEMM_SMEM = 3 * 32768;   // 96 KB

template <int RELU, int W32, int W16>
__global__ __launch_bounds__(256)
void gemm_mma(const __half* __restrict__ A, const __half* __restrict__ B,
              const float* __restrict__ bias, const float* __restrict__ res,
              float* __restrict__ C32, __half* __restrict__ C16,
              int M, int N, int K)
{
    extern __shared__ char smem[];
    uint32_t sb = smem_u32(smem);

    const int tid  = threadIdx.x;
    const int wid  = tid >> 5;
    const int lane = tid & 31;
    const int wm = (wid & 1) * 64;        // warp row offset in tile
    const int wn = (wid >> 1) * 32;       // warp col offset in tile
    const int row0 = blockIdx.y * 128;
    const int col0 = blockIdx.x * 128;
    const __half* Ab = A + (size_t)row0 * K;
    const __half* Bb = B + (size_t)col0 * K;
    const int nch = K >> 6;               // chunks of K=64

    auto load_chunk = [&](int c, int s) {
        uint32_t base = sb + (uint32_t)s * 32768u;
        const __half* Ap = Ab + c * 64;
        const __half* Bp = Bb + c * 64;
        #pragma unroll
        for (int j = 0; j < 4; j++) {
            int idx = tid + j * 256;              // 0..1023
            int r  = idx >> 3;
            int cc = idx & 7;
            uint32_t off = (uint32_t)(r * 128 + ((cc ^ (r & 7)) << 4));
            cp_async16(base + off,         Ap + (size_t)r * K + cc * 8);
            cp_async16(base + 16384 + off, Bp + (size_t)r * K + cc * 8);
        }
        asm volatile("cp.async.commit_group;" ::: "memory");
    };

    float acc[4][4][4];
    #pragma unroll
    for (int i = 0; i < 4; i++)
        #pragma unroll
        for (int j = 0; j < 4; j++)
            #pragma unroll
            for (int q = 0; q < 4; q++) acc[i][j][q] = 0.f;

    load_chunk(0, 0);
    load_chunk(1, 1);

    for (int i = 0; i < nch; i++) {
        if (i < nch - 1) asm volatile("cp.async.wait_group 1;" ::: "memory");
        else             asm volatile("cp.async.wait_group 0;" ::: "memory");
        __syncthreads();

        if (i + 2 < nch) load_chunk(i + 2, (i + 2) % 3);

        uint32_t abase = sb + (uint32_t)(i % 3) * 32768u;
        uint32_t bbase = abase + 16384;

        #pragma unroll
        for (int kk = 0; kk < 4; kk++) {          // 4 k-steps of 16
            uint32_t af[4][4];
            #pragma unroll
            for (int mt = 0; mt < 4; mt++) {
                int m  = wm + mt * 16 + (lane & 7) + ((lane >> 3) & 1) * 8;
                int kc = kk * 2 + (lane >> 4);
                ldmatrix_x4(af[mt],
                            abase + (uint32_t)(m * 128 + ((kc ^ (m & 7)) << 4)));
            }
            uint32_t bf[2][4];
            #pragma unroll
            for (int nb = 0; nb < 2; nb++) {
                int n  = wn + nb * 16 + (lane & 7) + (lane >> 4) * 8;
                int kc = kk * 2 + ((lane >> 3) & 1);
                ldmatrix_x4(bf[nb],
                            bbase + (uint32_t)(n * 128 + ((kc ^ (n & 7)) << 4)));
            }
            #pragma unroll
            for (int mt = 0; mt < 4; mt++)
                #pragma unroll
                for (int nt = 0; nt < 4; nt++)
                    mma16816(acc[mt][nt], af[mt], bf[nt >> 1] + (nt & 1) * 2);
        }
    }

    #pragma unroll
    for (int mt = 0; mt < 4; mt++) {
        #pragma unroll
        for (int h = 0; h < 2; h++) {
            int r = row0 + wm + mt * 16 + (lane >> 2) + h * 8;
            size_t rowN = (size_t)r * N;
            #pragma unroll
            for (int nt = 0; nt < 4; nt++) {
                int c = col0 + wn + nt * 8 + (lane & 3) * 2;
                float v0 = acc[mt][nt][h * 2 + 0];
                float v1 = acc[mt][nt][h * 2 + 1];
                if (bias) { v0 += bias[c]; v1 += bias[c + 1]; }
                if (res) {
                    float2 r2 = *reinterpret_cast<const float2*>(res + rowN + c);
                    v0 += r2.x; v1 += r2.y;
                }
                if (RELU) { v0 = fmaxf(v0, 0.f); v1 = fmaxf(v1, 0.f); }
                if (W32) {
                    float2 o = make_float2(v0, v1);
                    *reinterpret_cast<float2*>(C32 + rowN + c) = o;
                }
                if (W16) {
                    __half2 hh = __floats2half2_rn(v0, v1);
                    *reinterpret_cast<__half2*>(C16 + rowN + c) = hh;
                }
            }
        }
    }
}

// ---------------------------------------------------------------------------
// LayerNorm row body (shared by ln_kernel and prep_kernel)
// ---------------------------------------------------------------------------
__device__ __forceinline__ void ln_row(
    int row, int tid,
    const float* __restrict__ x, const float* __restrict__ g,
    const float* __restrict__ b, float* __restrict__ outf,
    __half* __restrict__ outh)
{
    const float* xr = x + (size_t)row * kD;

    float4 v = *reinterpret_cast<const float4*>(&xr[tid * 4]);
    float s  = v.x + v.y + v.z + v.w;
    float s2 = v.x * v.x + v.y * v.y + v.z * v.z + v.w * v.w;
    #pragma unroll
    for (int o = 16; o > 0; o >>= 1) {
        s  += __shfl_xor_sync(0xffffffffu, s,  o);
        s2 += __shfl_xor_sync(0xffffffffu, s2, o);
    }
    __shared__ float red[16];
    __shared__ float sh_mean, sh_rstd;
    int w = tid >> 5, l = tid & 31;
    if (l == 0) { red[w] = s; red[8 + w] = s2; }
    __syncthreads();
    if (tid == 0) {
        float S = 0.f, S2 = 0.f;
        #pragma unroll
        for (int i = 0; i < 8; i++) { S += red[i]; S2 += red[8 + i]; }
        float mean = S * (1.0f / kD);
        float var  = S2 * (1.0f / kD) - mean * mean;
        sh_mean = mean;
        sh_rstd = rsqrtf(var + 1e-5f);
    }
    __syncthreads();
    float mean = sh_mean, rstd = sh_rstd;
    float4 gv = *reinterpret_cast<const float4*>(&g[tid * 4]);
    float4 bv = *reinterpret_cast<const float4*>(&b[tid * 4]);
    float4 o4;
    o4.x = (v.x - mean) * rstd * gv.x + bv.x;
    o4.y = (v.y - mean) * rstd * gv.y + bv.y;
    o4.z = (v.z - mean) * rstd * gv.z + bv.z;
    o4.w = (v.w - mean) * rstd * gv.w + bv.w;
    *reinterpret_cast<float4*>(&outf[(size_t)row * kD + tid * 4]) = o4;
    __half2 h0 = __floats2half2_rn(o4.x, o4.y);
    __half2 h1 = __floats2half2_rn(o4.z, o4.w);
    uint2 u = make_uint2(*reinterpret_cast<uint32_t*>(&h0),
                         *reinterpret_cast<uint32_t*>(&h1));
    *reinterpret_cast<uint2*>(&outh[(size_t)row * kD + tid * 4]) = u;
}

__global__ __launch_bounds__(256) void ln_kernel(
    const float* __restrict__ x, const float* __restrict__ g,
    const float* __restrict__ b, float* __restrict__ outf,
    __half* __restrict__ outh)
{
    ln_row(blockIdx.x, threadIdx.x, x, g, b, outf, outh);
}

// ---------------------------------------------------------------------------
// Prep kernel: all 4 weight transposes (f32->f16) + LN1, one launch.
// Blocks [0,3072) wqkv, [3072,4096) w_proj, [4096,8192) w1, [8192,12288) w2,
// [12288, 12288+8192) LN1 rows.
// ---------------------------------------------------------------------------
constexpr int TRQKV = 3072;
constexpr int TRWP  = 1024;
constexpr int TRW1  = 4096;
constexpr int TRW2  = 4096;
constexpr int TR_TOTAL = TRQKV + TRWP + TRW1 + TRW2;   // 12288
constexpr int PREP_TOTAL = TR_TOTAL + kM;              // + 8192 LN rows

__global__ __launch_bounds__(256) void prep_kernel(
    const float* __restrict__ wq, const float* __restrict__ wk,
    const float* __restrict__ wv, const float* __restrict__ wp,
    const float* __restrict__ w1, const float* __restrict__ w2,
    __half* __restrict__ owqkv, __half* __restrict__ owp,
    __half* __restrict__ ow1,   __half* __restrict__ ow2,
    const float* __restrict__ x,  const float* __restrict__ g1,
    const float* __restrict__ be1, float* __restrict__ ln1f,
    __half* __restrict__ ln1h)
{
    int t = blockIdx.x;
    if (t >= TR_TOTAL) {
        ln_row(t - TR_TOTAL, threadIdx.x, x, g1, be1, ln1f, ln1h);
        return;
    }

    __shared__ float tile[32][33];
    const float* in;
    __half* out;
    int R, C, r0, c0;
    bool qkv = false;
    int sec = 0, h = 0;

    if (t < TRQKV) {
        qkv = true;
        int sh = t >> 6;                 // (sec,h) pair, 64 tiles each
        int tt = t & 63;
        sec = sh >> 4; h = sh & 15;
        in = ((sec == 0) ? wq : (sec == 1) ? wk : wv) + (size_t)h * kD * kE;
        R = kD; C = kE;
        r0 = (tt >> 1) * 32;             // d
        c0 = (tt & 1) * 32;              // e
        out = owqkv;
    } else if (t < TRQKV + TRWP) {
        t -= TRQKV; in = wp; out = owp; R = kD; C = kD;
        r0 = (t >> 5) * 32; c0 = (t & 31) * 32;
    } else if (t < TRQKV + TRWP + TRW1) {
        t -= TRQKV + TRWP; in = w1; out = ow1; R = kD; C = kF;
        r0 = (t >> 7) * 32; c0 = (t & 127) * 32;
    } else {
        t -= TRQKV + TRWP + TRW1; in = w2; out = ow2; R = kF; C = kD;
        r0 = (t >> 5) * 32; c0 = (t & 31) * 32;
    }

    int x2 = threadIdx.x & 31, y0 = threadIdx.x >> 5;
    #pragma unroll
    for (int j = 0; j < 32; j += 8)
        tile[y0 + j][x2] = in[(size_t)(r0 + y0 + j) * C + c0 + x2];
    __syncthreads();
    if (qkv) {
        #pragma unroll
        for (int j = 0; j < 32; j += 8)
            out[(size_t)(sec * kD + h * kE + c0 + y0 + j) * kD + r0 + x2] =
                __float2half(tile[x2][y0 + j]);
    } else {
        #pragma unroll
        for (int j = 0; j < 32; j += 8)
            out[(size_t)(c0 + y0 + j) * R + r0 + x2] =
                __float2half(tile[x2][y0 + j]);
    }
}

// ---------------------------------------------------------------------------
// Causal flash attention, f16 HMMA (FlashAttention-2 register pipeline).
// Block = 128 queries of one (b,h); 8 warps x 16 query rows; key tiles of 64.
// qb reversed so the longest CTAs launch first. exp2-domain softmax.
// Warps fully above the causal frontier of a tile skip it entirely.
// ---------------------------------------------------------------------------
constexpr int ATTN_SMEM = 16384 + 3 * 16384;   // 65536

__global__ __launch_bounds__(256) void attn_mma_kernel(
    const __half* __restrict__ QKV, __half* __restrict__ O)
{
    extern __shared__ char smem[];
    uint32_t sb = smem_u32(smem);
    uint32_t qsm = sb;

    const int qb = (int)gridDim.x - 1 - (int)blockIdx.x;   // long blocks first
    const int h = blockIdx.y, b = blockIdx.z;
    const int tid = threadIdx.x;
    const int wid = tid >> 5, lane = tid & 31;
    const int g  = lane >> 2, t4 = lane & 3;
    const int q0 = qb * 128;
    const int nt = 2 * qb + 2;              // key tiles of 64
    const int qrow0 = q0 + wid * 16;

    const __half* base = QKV + (size_t)(b * kT) * kQKVN + h * kE;

    // Q tile: 128 rows x 128B
    #pragma unroll
    for (int j = 0; j < 4; j++) {
        int idx = tid + j * 256;
        int r = idx >> 3, cc = idx & 7;
        uint32_t off = (uint32_t)(r * 128 + ((cc ^ (r & 7)) << 4));
        cp_async16(qsm + off, base + (size_t)(q0 + r) * kQKVN + cc * 8);
    }

    auto load_kv = [&](int j, int s) {
        uint32_t kb = sb + 16384 + (uint32_t)s * 16384u;
        const __half* Kp = base + kD;
        const __half* Vp = base + 2 * kD;
        #pragma unroll
        for (int jj = 0; jj < 2; jj++) {
            int idx = tid + jj * 256;
            int r = idx >> 3, cc = idx & 7;
            uint32_t off = (uint32_t)(r * 128 + ((cc ^ (r & 7)) << 4));
            cp_async16(kb + off,        Kp + (size_t)(j * 64 + r) * kQKVN + cc * 8);
            cp_async16(kb + 8192 + off, Vp + (size_t)(j * 64 + r) * kQKVN + cc * 8);
        }
        asm volatile("cp.async.commit_group;" ::: "memory");
    };

    load_kv(0, 0);
    load_kv(1, 1);

    uint32_t qf[4][4];
    float oacc[8][4];
    #pragma unroll
    for (int t = 0; t < 8; t++)
        #pragma unroll
        for (int q = 0; q < 4; q++) oacc[t][q] = 0.f;
    float m0 = -1e30f, m1 = -1e30f, l0 = 0.f, l1 = 0.f;
    // score scale folded with log2(e): S2 = (QK^T)*0.125*1.4426950
    const float scale2 = 0.125f * 1.44269504088896f;

    for (int i = 0; i < nt; i++) {
        if (i < nt - 1) asm volatile("cp.async.wait_group 1;" ::: "memory");
        else            asm volatile("cp.async.wait_group 0;" ::: "memory");
        __syncthreads();

        if (i == 0) {
            #pragma unroll
            for (int kc = 0; kc < 4; kc++) {
                int m  = wid * 16 + (lane & 7) + ((lane >> 3) & 1) * 8;
                int ch = kc * 2 + (lane >> 4);
                ldmatrix_x4(qf[kc],
                            qsm + (uint32_t)(m * 128 + ((ch ^ (m & 7)) << 4)));
            }
        }
        if (i + 2 < nt) load_kv(i + 2, (i + 2) % 3);

        const int j0 = i * 64;
        // Warp entirely above the causal frontier of this key tile:
        // every score is masked -> P == 0 -> skip all compute (f=1, sum=0).
        if (j0 > qrow0 + 15) continue;

        uint32_t kb = sb + 16384 + (uint32_t)(i % 3) * 16384u;
        uint32_t vb = kb + 8192;

        // ---- S = Q K^T ----
        float sacc[8][4];
        #pragma unroll
        for (int t = 0; t < 8; t++)
            #pragma unroll
            for (int q = 0; q < 4; q++) sacc[t][q] = 0.f;

        #pragma unroll
        for (int kc = 0; kc < 4; kc++) {
            #pragma unroll
            for (int np = 0; np < 4; np++) {
                int n  = np * 16 + (lane & 7) + (lane >> 4) * 8;
                int ch = kc * 2 + ((lane >> 3) & 1);
                uint32_t bf[4];
                ldmatrix_x4(bf, kb + (uint32_t)(n * 128 + ((ch ^ (n & 7)) << 4)));
                mma16816(sacc[np * 2 + 0], qf[kc], bf);
                mma16816(sacc[np * 2 + 1], qf[kc], bf + 2);
            }
        }

        // ---- scale (exp2 domain) + causal mask ----
        const int gr0 = qrow0 + g, gr1 = gr0 + 8;
        const bool need_mask = (j0 + 63 > qrow0);
        #pragma unroll
        for (int t = 0; t < 8; t++) {
            int gc = j0 + t * 8 + t4 * 2;
            float s0 = sacc[t][0] * scale2, s1 = sacc[t][1] * scale2;
            float s2 = sacc[t][2] * scale2, s3 = sacc[t][3] * scale2;
            if (need_mask) {
                if (gc     > gr0) s0 = -1e30f;
                if (gc + 1 > gr0) s1 = -1e30f;
                if (gc     > gr1) s2 = -1e30f;
                if (gc + 1 > gr1) s3 = -1e30f;
            }
            sacc[t][0] = s0; sacc[t][1] = s1; sacc[t][2] = s2; sacc[t][3] = s3;
        }

        // ---- online softmax (base-2; quad reduction over lanes t4) ----
        float rmax0 = -1e30f, rmax1 = -1e30f;
        #pragma unroll
        for (int t = 0; t < 8; t++) {
            rmax0 = fmaxf(rmax0, fmaxf(sacc[t][0], sacc[t][1]));
            rmax1 = fmaxf(rmax1, fmaxf(sacc[t][2], sacc[t][3]));
        }
        rmax0 = fmaxf(rmax0, __shfl_xor_sync(0xffffffffu, rmax0, 1));
        rmax0 = fmaxf(rmax0, __shfl_xor_sync(0xffffffffu, rmax0, 2));
        rmax1 = fmaxf(rmax1, __shfl_xor_sync(0xffffffffu, rmax1, 1));
        rmax1 = fmaxf(rmax1, __shfl_xor_sync(0xffffffffu, rmax1, 2));

        float mn0 = fmaxf(m0, rmax0), mn1 = fmaxf(m1, rmax1);
        float f0 = ex2(m0 - mn0),  f1 = ex2(m1 - mn1);
        float sum0 = 0.f, sum1 = 0.f;
        #pragma unroll
        for (int t = 0; t < 8; t++) {
            float p0 = ex2(sacc[t][0] - mn0);
            float p1 = ex2(sacc[t][1] - mn0);
            float p2 = ex2(sacc[t][2] - mn1);
            float p3 = ex2(sacc[t][3] - mn1);
            sacc[t][0] = p0; sacc[t][1] = p1; sacc[t][2] = p2; sacc[t][3] = p3;
            sum0 += p0 + p1; sum1 += p2 + p3;
        }
        sum0 += __shfl_xor_sync(0xffffffffu, sum0, 1);
        sum0 += __shfl_xor_sync(0xffffffffu, sum0, 2);
        sum1 += __shfl_xor_sync(0xffffffffu, sum1, 1);
        sum1 += __shfl_xor_sync(0xffffffffu, sum1, 2);
        l0 = l0 * f0 + sum0; m0 = mn0;
        l1 = l1 * f1 + sum1; m1 = mn1;

        #pragma unroll
        for (int t = 0; t < 8; t++) {
            oacc[t][0] *= f0; oacc[t][1] *= f0;
            oacc[t][2] *= f1; oacc[t][3] *= f1;
        }

        // ---- O += P V ----
        #pragma unroll
        for (int kc = 0; kc < 4; kc++) {
            uint32_t pa[4];
            pa[0] = packh2(sacc[2 * kc][0],     sacc[2 * kc][1]);
            pa[1] = packh2(sacc[2 * kc][2],     sacc[2 * kc][3]);
            pa[2] = packh2(sacc[2 * kc + 1][0], sacc[2 * kc + 1][1]);
            pa[3] = packh2(sacc[2 * kc + 1][2], sacc[2 * kc + 1][3]);
            #pragma unroll
            for (int np = 0; np < 4; np++) {
                int kk = kc * 16 + (lane & 7) + ((lane >> 3) & 1) * 8;  // V row
                int ch = np * 2 + (lane >> 4);                          // E chunk
                uint32_t bf[4];
                ldmatrix_x4_trans(bf,
                    vb + (uint32_t)(kk * 128 + ((ch ^ (kk & 7)) << 4)));
                mma16816(oacc[np * 2 + 0], pa, bf);
                mma16816(oacc[np * 2 + 1], pa, bf + 2);
            }
        }
    }

    // ---- normalize + write ----
    float inv0 = 1.0f / l0, inv1 = 1.0f / l1;
    size_t row0 = (size_t)(b * kT + qrow0 + g) * kD;
    size_t row1 = row0 + (size_t)8 * kD;
    #pragma unroll
    for (int t = 0; t < 8; t++) {
        int col = h * kE + t * 8 + t4 * 2;
        __half2 o0 = __floats2half2_rn(oacc[t][0] * inv0, oacc[t][1] * inv0);
        __half2 o1 = __floats2half2_rn(oacc[t][2] * inv1, oacc[t][3] * inv1);
        *reinterpret_cast<__half2*>(O + row0 + col) = o0;
        *reinterpret_cast<__half2*>(O + row1 + col) = o1;
    }
}

// ---------------------------------------------------------------------------
// Launch
// ---------------------------------------------------------------------------
extern "C" void kernel_launch(void* const* d_in, const int* in_sizes, int n_in,
                              void* d_out, int out_size)
{
    const float* x      = (const float*)d_in[0];
    const float* wq     = (const float*)d_in[1];
    const float* wk     = (const float*)d_in[2];
    const float* wv     = (const float*)d_in[3];
    const float* w_proj = (const float*)d_in[4];
    const float* b_proj = (const float*)d_in[5];
    const float* w1     = (const float*)d_in[6];
    const float* b1     = (const float*)d_in[7];
    const float* w2     = (const float*)d_in[8];
    const float* b2     = (const float*)d_in[9];
    const float* g1     = (const float*)d_in[10];
    const float* be1    = (const float*)d_in[11];
    const float* g2     = (const float*)d_in[12];
    const float* be2    = (const float*)d_in[13];
    float* out = (float*)d_out;

    float  *ln1f, *x2, *ln2f;
    __half *ln1h, *qkvh, *atth, *ln2h, *hidh, *wqkvh, *wph, *w1t, *w2t;
    cudaGetSymbolAddress((void**)&ln1f,  g_ln1f);
    cudaGetSymbolAddress((void**)&ln1h,  g_ln1h);
    cudaGetSymbolAddress((void**)&qkvh,  g_qkvh);
    cudaGetSymbolAddress((void**)&atth,  g_atth);
    cudaGetSymbolAddress((void**)&x2,    g_x2);
    cudaGetSymbolAddress((void**)&ln2f,  g_ln2f);
    cudaGetSymbolAddress((void**)&ln2h,  g_ln2h);
    cudaGetSymbolAddress((void**)&hidh,  g_hidh);
    cudaGetSymbolAddress((void**)&wqkvh, g_wqkv);
    cudaGetSymbolAddress((void**)&wph,   g_wp);
    cudaGetSymbolAddress((void**)&w1t,   g_w1t);
    cudaGetSymbolAddress((void**)&w2t,   g_w2t);

    cudaFuncSetAttribute(attn_mma_kernel,
                         cudaFuncAttributeMaxDynamicSharedMemorySize, ATTN_SMEM);
    cudaFuncSetAttribute(gemm_mma<0, 1, 0>,
                         cudaFuncAttributeMaxDynamicSharedMemorySize, GEMM_SMEM);
    cudaFuncSetAttribute(gemm_mma<0, 0, 1>,
                         cudaFuncAttributeMaxDynamicSharedMemorySize, GEMM_SMEM);
    cudaFuncSetAttribute(gemm_mma<1, 0, 1>,
                         cudaFuncAttributeMaxDynamicSharedMemorySize, GEMM_SMEM);

    // 1) Prep: all weight transposes + LN1 in one launch
    prep_kernel<<<PREP_TOTAL, 256>>>(wq, wk, wv, w_proj, w1, w2,
                                     wqkvh, wph, w1t, w2t,
                                     x, g1, be1, ln1f, ln1h);

    // 2) QKV GEMM: [8192,1024] @ [3072,1024]^T -> f16
    gemm_mma<0, 0, 1><<<dim3(kQKVN / 128, kM / 128), 256, GEMM_SMEM>>>(
        ln1h, wqkvh, nullptr, nullptr, nullptr, qkvh, kM, kQKVN, kD);

    // 3) Causal flash attention (f16 HMMA) -> f16
    attn_mma_kernel<<<dim3(kT / 128, kH, kB), 256, ATTN_SMEM>>>(qkvh, atth);

    // 4) Output projection + bias + residual(ln1) -> x2 (f32)
    gemm_mma<0, 1, 0><<<dim3(kD / 128, kM / 128), 256, GEMM_SMEM>>>(
        atth, wph, b_proj, ln1f, x2, nullptr, kM, kD, kD);

    // 5) LN2
    ln_kernel<<<kM, 256>>>(x2, g2, be2, ln2f, ln2h);

    // 6) FFN1 + ReLU -> f16 hidden
    gemm_mma<1, 0, 1><<<dim3(kF / 128, kM / 128), 256, GEMM_SMEM>>>(
        ln2h, w1t, b1, nullptr, nullptr, hidh, kM, kF, kD);

    // 7) FFN2 + bias + residual(ln2) -> output (f32)
    gemm_mma<0, 1, 0><<<dim3(kD / 128, kM / 128), 256, GEMM_SMEM>>>(
        hidh, w2t, b2, ln2f, out, nullptr, kM, kD, kF);
}

// round 13
// speedup vs baseline: 1.5637x; 1.0486x over previous
#include <cuda_runtime.h>
#include <cuda_fp16.h>
#include <cstdint>

// ---------------------------------------------------------------------------
// Problem constants
// ---------------------------------------------------------------------------
constexpr int kB = 8;
constexpr int kT = 1024;
constexpr int kD = 1024;          // n_embd
constexpr int kH = 16;            // heads
constexpr int kE = 64;            // head size
constexpr int kF = 4096;          // ffn hidden
constexpr int kM = kB * kT;       // 8192 rows
constexpr int kQKVN = 3 * kD;     // 3072

// ---------------------------------------------------------------------------
// Scratch (device globals: allocation-free per harness rules)
// ---------------------------------------------------------------------------
__device__ __align__(16) __half g_ln1h[(size_t)kM * kD];
__device__ __align__(16) __half g_qkvh[(size_t)kM * kQKVN];
__device__ __align__(16) __half g_atth[(size_t)kM * kD];
__device__ __align__(16) __half g_x2h [(size_t)kM * kD];
__device__ __align__(16) __half g_ln2h[(size_t)kM * kD];
__device__ __align__(16) __half g_hidh[(size_t)kM * kF];
__device__ __align__(16) __half g_wqkv[(size_t)kQKVN * kD];   // [N=3072][K=1024]
__device__ __align__(16) __half g_wp  [(size_t)kD * kD];      // [N=1024][K=1024]
__device__ __align__(16) __half g_w1t [(size_t)kF * kD];      // [N=4096][K=1024]
__device__ __align__(16) __half g_w2t [(size_t)kD * kF];      // [N=1024][K=4096]

// ---------------------------------------------------------------------------
// Low-level helpers
// ---------------------------------------------------------------------------
__device__ __forceinline__ uint32_t smem_u32(const void* p) {
    uint32_t r;
    asm("{ .reg .u64 t; cvta.to.shared.u64 t, %1; cvt.u32.u64 %0, t; }"
        : "=r"(r) : "l"(p));
    return r;
}

__device__ __forceinline__ void cp_async16(uint32_t dst, const void* src) {
    asm volatile("cp.async.cg.shared.global [%0], [%1], 16;"
                 :: "r"(dst), "l"(src));
}

__device__ __forceinline__ void ldmatrix_x4(uint32_t* r, uint32_t addr) {
    asm volatile("ldmatrix.sync.aligned.m8n8.x4.shared.b16 {%0,%1,%2,%3}, [%4];"
                 : "=r"(r[0]), "=r"(r[1]), "=r"(r[2]), "=r"(r[3]) : "r"(addr));
}

__device__ __forceinline__ void ldmatrix_x4_trans(uint32_t* r, uint32_t addr) {
    asm volatile("ldmatrix.sync.aligned.m8n8.x4.trans.shared.b16 {%0,%1,%2,%3}, [%4];"
                 : "=r"(r[0]), "=r"(r[1]), "=r"(r[2]), "=r"(r[3]) : "r"(addr));
}

__device__ __forceinline__ void mma16816(float* d,
                                         const uint32_t* a, const uint32_t* b) {
    asm volatile(
        "mma.sync.aligned.m16n8k16.row.col.f32.f16.f16.f32 "
        "{%0,%1,%2,%3}, {%4,%5,%6,%7}, {%8,%9}, {%0,%1,%2,%3};"
        : "+f"(d[0]), "+f"(d[1]), "+f"(d[2]), "+f"(d[3])
        : "r"(a[0]), "r"(a[1]), "r"(a[2]), "r"(a[3]), "r"(b[0]), "r"(b[1]));
}

__device__ __forceinline__ uint32_t packh2(float a, float b) {
    __half2 h = __floats2half2_rn(a, b);
    return *reinterpret_cast<uint32_t*>(&h);
}

__device__ __forceinline__ float ex2(float x) {
    float y;
    asm("ex2.approx.ftz.f32 %0, %1;" : "=f"(y) : "f"(x));
    return y;
}

// ---------------------------------------------------------------------------
// HMMA GEMM: C[M,N] = A_h[M,K] @ B_h[N,K]^T  (+bias f32) (+res f16) (relu)
// 128x128 block tile, BK=64, 3-stage cp.async pipeline, 256 threads (8 warps,
// 64x32 warp tiles, 2 CTAs/SM -> 16 warps/SM). Smem: 128 rows x 128B,
// XOR-swizzled.  [Proven round-9 inner loop — unchanged.]
// ---------------------------------------------------------------------------
constexpr int GEMM_SMEM = 3 * 32768;   // 96 KB

template <int RELU, int W32, int W16>
__global__ __launch_bounds__(256)
void gemm_mma(const __half* __restrict__ A, const __half* __restrict__ B,
              const float* __restrict__ bias, const __half* __restrict__ res,
              float* __restrict__ C32, __half* __restrict__ C16,
              int M, int N, int K)
{
    extern __shared__ char smem[];
    uint32_t sb = smem_u32(smem);

    const int tid  = threadIdx.x;
    const int wid  = tid >> 5;
    const int lane = tid & 31;
    const int wm = (wid & 1) * 64;        // warp row offset in tile
    const int wn = (wid >> 1) * 32;       // warp col offset in tile
    const int row0 = blockIdx.y * 128;
    const int col0 = blockIdx.x * 128;
    const __half* Ab = A + (size_t)row0 * K;
    const __half* Bb = B + (size_t)col0 * K;
    const int nch = K >> 6;               // chunks of K=64

    auto load_chunk = [&](int c, int s) {
        uint32_t base = sb + (uint32_t)s * 32768u;
        const __half* Ap = Ab + c * 64;
        const __half* Bp = Bb + c * 64;
        #pragma unroll
        for (int j = 0; j < 4; j++) {
            int idx = tid + j * 256;              // 0..1023
            int r  = idx >> 3;
            int cc = idx & 7;
            uint32_t off = (uint32_t)(r * 128 + ((cc ^ (r & 7)) << 4));
            cp_async16(base + off,         Ap + (size_t)r * K + cc * 8);
            cp_async16(base + 16384 + off, Bp + (size_t)r * K + cc * 8);
        }
        asm volatile("cp.async.commit_group;" ::: "memory");
    };

    float acc[4][4][4];
    #pragma unroll
    for (int i = 0; i < 4; i++)
        #pragma unroll
        for (int j = 0; j < 4; j++)
            #pragma unroll
            for (int q = 0; q < 4; q++) acc[i][j][q] = 0.f;

    load_chunk(0, 0);
    load_chunk(1, 1);

    for (int i = 0; i < nch; i++) {
        if (i < nch - 1) asm volatile("cp.async.wait_group 1;" ::: "memory");
        else             asm volatile("cp.async.wait_group 0;" ::: "memory");
        __syncthreads();

        if (i + 2 < nch) load_chunk(i + 2, (i + 2) % 3);

        uint32_t abase = sb + (uint32_t)(i % 3) * 32768u;
        uint32_t bbase = abase + 16384;

        #pragma unroll
        for (int kk = 0; kk < 4; kk++) {          // 4 k-steps of 16
            uint32_t af[4][4];
            #pragma unroll
            for (int mt = 0; mt < 4; mt++) {
                int m  = wm + mt * 16 + (lane & 7) + ((lane >> 3) & 1) * 8;
                int kc = kk * 2 + (lane >> 4);
                ldmatrix_x4(af[mt],
                            abase + (uint32_t)(m * 128 + ((kc ^ (m & 7)) << 4)));
            }
            uint32_t bf[2][4];
            #pragma unroll
            for (int nb = 0; nb < 2; nb++) {
                int n  = wn + nb * 16 + (lane & 7) + (lane >> 4) * 8;
                int kc = kk * 2 + ((lane >> 3) & 1);
                ldmatrix_x4(bf[nb],
                            bbase + (uint32_t)(n * 128 + ((kc ^ (n & 7)) << 4)));
            }
            #pragma unroll
            for (int mt = 0; mt < 4; mt++)
                #pragma unroll
                for (int nt = 0; nt < 4; nt++)
                    mma16816(acc[mt][nt], af[mt], bf[nt >> 1] + (nt & 1) * 2);
        }
    }

    #pragma unroll
    for (int mt = 0; mt < 4; mt++) {
        #pragma unroll
        for (int h = 0; h < 2; h++) {
            int r = row0 + wm + mt * 16 + (lane >> 2) + h * 8;
            size_t rowN = (size_t)r * N;
            #pragma unroll
            for (int nt = 0; nt < 4; nt++) {
                int c = col0 + wn + nt * 8 + (lane & 3) * 2;
                float v0 = acc[mt][nt][h * 2 + 0];
                float v1 = acc[mt][nt][h * 2 + 1];
                if (bias) { v0 += bias[c]; v1 += bias[c + 1]; }
                if (res) {
                    __half2 r2 = *reinterpret_cast<const __half2*>(res + rowN + c);
                    float2 rf = __half22float2(r2);
                    v0 += rf.x; v1 += rf.y;
                }
                if (RELU) { v0 = fmaxf(v0, 0.f); v1 = fmaxf(v1, 0.f); }
                if (W32) {
                    float2 o = make_float2(v0, v1);
                    *reinterpret_cast<float2*>(C32 + rowN + c) = o;
                }
                if (W16) {
                    __half2 hh = __floats2half2_rn(v0, v1);
                    *reinterpret_cast<__half2*>(C16 + rowN + c) = hh;
                }
            }
        }
    }
}

// ---------------------------------------------------------------------------
// LayerNorm row bodies: f32 input (LN1, inside prep) and f16 input (LN2).
// Output f16 only.
// ---------------------------------------------------------------------------
__device__ __forceinline__ void ln_finish(
    int row, int tid, float4 v,
    const float* __restrict__ g, const float* __restrict__ b,
    __half* __restrict__ outh)
{
    float s  = v.x + v.y + v.z + v.w;
    float s2 = v.x * v.x + v.y * v.y + v.z * v.z + v.w * v.w;
    #pragma unroll
    for (int o = 16; o > 0; o >>= 1) {
        s  += __shfl_xor_sync(0xffffffffu, s,  o);
        s2 += __shfl_xor_sync(0xffffffffu, s2, o);
    }
    __shared__ float red[16];
    __shared__ float sh_mean, sh_rstd;
    int w = tid >> 5, l = tid & 31;
    if (l == 0) { red[w] = s; red[8 + w] = s2; }
    __syncthreads();
    if (tid == 0) {
        float S = 0.f, S2 = 0.f;
        #pragma unroll
        for (int i = 0; i < 8; i++) { S += red[i]; S2 += red[8 + i]; }
        float mean = S * (1.0f / kD);
        float var  = S2 * (1.0f / kD) - mean * mean;
        sh_mean = mean;
        sh_rstd = rsqrtf(var + 1e-5f);
    }
    __syncthreads();
    float mean = sh_mean, rstd = sh_rstd;
    float4 gv = *reinterpret_cast<const float4*>(&g[tid * 4]);
    float4 bv = *reinterpret_cast<const float4*>(&b[tid * 4]);
    float o0 = (v.x - mean) * rstd * gv.x + bv.x;
    float o1 = (v.y - mean) * rstd * gv.y + bv.y;
    float o2 = (v.z - mean) * rstd * gv.z + bv.z;
    float o3 = (v.w - mean) * rstd * gv.w + bv.w;
    __half2 h0 = __floats2half2_rn(o0, o1);
    __half2 h1 = __floats2half2_rn(o2, o3);
    uint2 u = make_uint2(*reinterpret_cast<uint32_t*>(&h0),
                         *reinterpret_cast<uint32_t*>(&h1));
    *reinterpret_cast<uint2*>(&outh[(size_t)row * kD + tid * 4]) = u;
}

__device__ __forceinline__ void ln_row_f32(
    int row, int tid, const float* __restrict__ x,
    const float* __restrict__ g, const float* __restrict__ b,
    __half* __restrict__ outh)
{
    float4 v = *reinterpret_cast<const float4*>(x + (size_t)row * kD + tid * 4);
    ln_finish(row, tid, v, g, b, outh);
}

__global__ __launch_bounds__(256) void ln_h_kernel(
    const __half* __restrict__ x, const float* __restrict__ g,
    const float* __restrict__ b, __half* __restrict__ outh)
{
    int row = blockIdx.x, tid = threadIdx.x;
    uint2 raw = *reinterpret_cast<const uint2*>(x + (size_t)row * kD + tid * 4);
    float2 a = __half22float2(*reinterpret_cast<__half2*>(&raw.x));
    float2 c = __half22float2(*reinterpret_cast<__half2*>(&raw.y));
    ln_finish(row, tid, make_float4(a.x, a.y, c.x, c.y), g, b, outh);
}

// ---------------------------------------------------------------------------
// Prep kernel: all 4 weight transposes (f32->f16) + LN1, one launch.
// ---------------------------------------------------------------------------
constexpr int TRQKV = 3072;
constexpr int TRWP  = 1024;
constexpr int TRW1  = 4096;
constexpr int TRW2  = 4096;
constexpr int TR_TOTAL = TRQKV + TRWP + TRW1 + TRW2;   // 12288
constexpr int PREP_TOTAL = TR_TOTAL + kM;              // + 8192 LN rows

__global__ __launch_bounds__(256) void prep_kernel(
    const float* __restrict__ wq, const float* __restrict__ wk,
    const float* __restrict__ wv, const float* __restrict__ wp,
    const float* __restrict__ w1, const float* __restrict__ w2,
    __half* __restrict__ owqkv, __half* __restrict__ owp,
    __half* __restrict__ ow1,   __half* __restrict__ ow2,
    const float* __restrict__ x,  const float* __restrict__ g1,
    const float* __restrict__ be1, __half* __restrict__ ln1h)
{
    int t = blockIdx.x;
    if (t >= TR_TOTAL) {
        ln_row_f32(t - TR_TOTAL, threadIdx.x, x, g1, be1, ln1h);
        return;
    }

    __shared__ float tile[32][33];
    const float* in;
    __half* out;
    int R, C, r0, c0;
    bool qkv = false;
    int sec = 0, h = 0;

    if (t < TRQKV) {
        qkv = true;
        int sh = t >> 6;                 // (sec,h) pair, 64 tiles each
        int tt = t & 63;
        sec = sh >> 4; h = sh & 15;
        in = ((sec == 0) ? wq : (sec == 1) ? wk : wv) + (size_t)h * kD * kE;
        R = kD; C = kE;
        r0 = (tt >> 1) * 32;             // d
        c0 = (tt & 1) * 32;              // e
        out = owqkv;
    } else if (t < TRQKV + TRWP) {
        t -= TRQKV; in = wp; out = owp; R = kD; C = kD;
        r0 = (t >> 5) * 32; c0 = (t & 31) * 32;
    } else if (t < TRQKV + TRWP + TRW1) {
        t -= TRQKV + TRWP; in = w1; out = ow1; R = kD; C = kF;
        r0 = (t >> 7) * 32; c0 = (t & 127) * 32;
    } else {
        t -= TRQKV + TRWP + TRW1; in = w2; out = ow2; R = kF; C = kD;
        r0 = (t >> 5) * 32; c0 = (t & 31) * 32;
    }

    int x2 = threadIdx.x & 31, y0 = threadIdx.x >> 5;
    #pragma unroll
    for (int j = 0; j < 32; j += 8)
        tile[y0 + j][x2] = in[(size_t)(r0 + y0 + j) * C + c0 + x2];
    __syncthreads();
    if (qkv) {
        #pragma unroll
        for (int j = 0; j < 32; j += 8)
            out[(size_t)(sec * kD + h * kE + c0 + y0 + j) * kD + r0 + x2] =
                __float2half(tile[x2][y0 + j]);
    } else {
        #pragma unroll
        for (int j = 0; j < 32; j += 8)
            out[(size_t)(c0 + y0 + j) * R + r0 + x2] =
                __float2half(tile[x2][y0 + j]);
    }
}

// ---------------------------------------------------------------------------
// Causal flash attention, f16 HMMA (FlashAttention-2 register pipeline).
// Block = 128 queries of one (b,h); 8 warps x 16 query rows; key tiles of 64.
// qb reversed so the longest CTAs launch first. exp2-domain softmax.
// Warps fully above the causal frontier of a tile skip it entirely.
// ---------------------------------------------------------------------------
constexpr int ATTN_SMEM = 16384 + 3 * 16384;   // 65536

__global__ __launch_bounds__(256) void attn_mma_kernel(
    const __half* __restrict__ QKV, __half* __restrict__ O)
{
    extern __shared__ char smem[];
    uint32_t sb = smem_u32(smem);
    uint32_t qsm = sb;

    const int qb = (int)gridDim.x - 1 - (int)blockIdx.x;   // long blocks first
    const int h = blockIdx.y, b = blockIdx.z;
    const int tid = threadIdx.x;
    const int wid = tid >> 5, lane = tid & 31;
    const int g  = lane >> 2, t4 = lane & 3;
    const int q0 = qb * 128;
    const int nt = 2 * qb + 2;              // key tiles of 64
    const int qrow0 = q0 + wid * 16;

    const __half* base = QKV + (size_t)(b * kT) * kQKVN + h * kE;

    // Q tile: 128 rows x 128B
    #pragma unroll
    for (int j = 0; j < 4; j++) {
        int idx = tid + j * 256;
        int r = idx >> 3, cc = idx & 7;
        uint32_t off = (uint32_t)(r * 128 + ((cc ^ (r & 7)) << 4));
        cp_async16(qsm + off, base + (size_t)(q0 + r) * kQKVN + cc * 8);
    }

    auto load_kv = [&](int j, int s) {
        uint32_t kb = sb + 16384 + (uint32_t)s * 16384u;
        const __half* Kp = base + kD;
        const __half* Vp = base + 2 * kD;
        #pragma unroll
        for (int jj = 0; jj < 2; jj++) {
            int idx = tid + jj * 256;
            int r = idx >> 3, cc = idx & 7;
            uint32_t off = (uint32_t)(r * 128 + ((cc ^ (r & 7)) << 4));
            cp_async16(kb + off,        Kp + (size_t)(j * 64 + r) * kQKVN + cc * 8);
            cp_async16(kb + 8192 + off, Vp + (size_t)(j * 64 + r) * kQKVN + cc * 8);
        }
        asm volatile("cp.async.commit_group;" ::: "memory");
    };

    load_kv(0, 0);
    load_kv(1, 1);

    uint32_t qf[4][4];
    float oacc[8][4];
    #pragma unroll
    for (int t = 0; t < 8; t++)
        #pragma unroll
        for (int q = 0; q < 4; q++) oacc[t][q] = 0.f;
    float m0 = -1e30f, m1 = -1e30f, l0 = 0.f, l1 = 0.f;
    // score scale folded with log2(e): S2 = (QK^T)*0.125*1.4426950
    const float scale2 = 0.125f * 1.44269504088896f;

    for (int i = 0; i < nt; i++) {
        if (i < nt - 1) asm volatile("cp.async.wait_group 1;" ::: "memory");
        else            asm volatile("cp.async.wait_group 0;" ::: "memory");
        __syncthreads();

        if (i == 0) {
            #pragma unroll
            for (int kc = 0; kc < 4; kc++) {
                int m  = wid * 16 + (lane & 7) + ((lane >> 3) & 1) * 8;
                int ch = kc * 2 + (lane >> 4);
                ldmatrix_x4(qf[kc],
                            qsm + (uint32_t)(m * 128 + ((ch ^ (m & 7)) << 4)));
            }
        }
        if (i + 2 < nt) load_kv(i + 2, (i + 2) % 3);

        const int j0 = i * 64;
        // Warp entirely above the causal frontier: P == 0 -> skip.
        if (j0 > qrow0 + 15) continue;

        uint32_t kb = sb + 16384 + (uint32_t)(i % 3) * 16384u;
        uint32_t vb = kb + 8192;

        // ---- S = Q K^T ----
        float sacc[8][4];
        #pragma unroll
        for (int t = 0; t < 8; t++)
            #pragma unroll
            for (int q = 0; q < 4; q++) sacc[t][q] = 0.f;

        #pragma unroll
        for (int kc = 0; kc < 4; kc++) {
            #pragma unroll
            for (int np = 0; np < 4; np++) {
                int n  = np * 16 + (lane & 7) + (lane >> 4) * 8;
                int ch = kc * 2 + ((lane >> 3) & 1);
                uint32_t bf[4];
                ldmatrix_x4(bf, kb + (uint32_t)(n * 128 + ((ch ^ (n & 7)) << 4)));
                mma16816(sacc[np * 2 + 0], qf[kc], bf);
                mma16816(sacc[np * 2 + 1], qf[kc], bf + 2);
            }
        }

        // ---- scale (exp2 domain) + causal mask ----
        const int gr0 = qrow0 + g, gr1 = gr0 + 8;
        const bool need_mask = (j0 + 63 > qrow0);
        #pragma unroll
        for (int t = 0; t < 8; t++) {
            int gc = j0 + t * 8 + t4 * 2;
            float s0 = sacc[t][0] * scale2, s1 = sacc[t][1] * scale2;
            float s2 = sacc[t][2] * scale2, s3 = sacc[t][3] * scale2;
            if (need_mask) {
                if (gc     > gr0) s0 = -1e30f;
                if (gc + 1 > gr0) s1 = -1e30f;
                if (gc     > gr1) s2 = -1e30f;
                if (gc + 1 > gr1) s3 = -1e30f;
            }
            sacc[t][0] = s0; sacc[t][1] = s1; sacc[t][2] = s2; sacc[t][3] = s3;
        }

        // ---- online softmax (base-2; quad reduction over lanes t4) ----
        float rmax0 = -1e30f, rmax1 = -1e30f;
        #pragma unroll
        for (int t = 0; t < 8; t++) {
            rmax0 = fmaxf(rmax0, fmaxf(sacc[t][0], sacc[t][1]));
            rmax1 = fmaxf(rmax1, fmaxf(sacc[t][2], sacc[t][3]));
        }
        rmax0 = fmaxf(rmax0, __shfl_xor_sync(0xffffffffu, rmax0, 1));
        rmax0 = fmaxf(rmax0, __shfl_xor_sync(0xffffffffu, rmax0, 2));
        rmax1 = fmaxf(rmax1, __shfl_xor_sync(0xffffffffu, rmax1, 1));
        rmax1 = fmaxf(rmax1, __shfl_xor_sync(0xffffffffu, rmax1, 2));

        float mn0 = fmaxf(m0, rmax0), mn1 = fmaxf(m1, rmax1);
        float f0 = ex2(m0 - mn0),  f1 = ex2(m1 - mn1);
        float sum0 = 0.f, sum1 = 0.f;
        #pragma unroll
        for (int t = 0; t < 8; t++) {
            float p0 = ex2(sacc[t][0] - mn0);
            float p1 = ex2(sacc[t][1] - mn0);
            float p2 = ex2(sacc[t][2] - mn1);
            float p3 = ex2(sacc[t][3] - mn1);
            sacc[t][0] = p0; sacc[t][1] = p1; sacc[t][2] = p2; sacc[t][3] = p3;
            sum0 += p0 + p1; sum1 += p2 + p3;
        }
        sum0 += __shfl_xor_sync(0xffffffffu, sum0, 1);
        sum0 += __shfl_xor_sync(0xffffffffu, sum0, 2);
        sum1 += __shfl_xor_sync(0xffffffffu, sum1, 1);
        sum1 += __shfl_xor_sync(0xffffffffu, sum1, 2);
        l0 = l0 * f0 + sum0; m0 = mn0;
        l1 = l1 * f1 + sum1; m1 = mn1;

        #pragma unroll
        for (int t = 0; t < 8; t++) {
            oacc[t][0] *= f0; oacc[t][1] *= f0;
            oacc[t][2] *= f1; oacc[t][3] *= f1;
        }

        // ---- O += P V ----
        #pragma unroll
        for (int kc = 0; kc < 4; kc++) {
            uint32_t pa[4];
            pa[0] = packh2(sacc[2 * kc][0],     sacc[2 * kc][1]);
            pa[1] = packh2(sacc[2 * kc][2],     sacc[2 * kc][3]);
            pa[2] = packh2(sacc[2 * kc + 1][0], sacc[2 * kc + 1][1]);
            pa[3] = packh2(sacc[2 * kc + 1][2], sacc[2 * kc + 1][3]);
            #pragma unroll
            for (int np = 0; np < 4; np++) {
                int kk = kc * 16 + (lane & 7) + ((lane >> 3) & 1) * 8;  // V row
                int ch = np * 2 + (lane >> 4);                          // E chunk
                uint32_t bf[4];
                ldmatrix_x4_trans(bf,
                    vb + (uint32_t)(kk * 128 + ((ch ^ (kk & 7)) << 4)));
                mma16816(oacc[np * 2 + 0], pa, bf);
                mma16816(oacc[np * 2 + 1], pa, bf + 2);
            }
        }
    }

    // ---- normalize + write ----
    float inv0 = 1.0f / l0, inv1 = 1.0f / l1;
    size_t row0 = (size_t)(b * kT + qrow0 + g) * kD;
    size_t row1 = row0 + (size_t)8 * kD;
    #pragma unroll
    for (int t = 0; t < 8; t++) {
        int col = h * kE + t * 8 + t4 * 2;
        __half2 o0 = __floats2half2_rn(oacc[t][0] * inv0, oacc[t][1] * inv0);
        __half2 o1 = __floats2half2_rn(oacc[t][2] * inv1, oacc[t][3] * inv1);
        *reinterpret_cast<__half2*>(O + row0 + col) = o0;
        *reinterpret_cast<__half2*>(O + row1 + col) = o1;
    }
}

// ---------------------------------------------------------------------------
// Launch
// ---------------------------------------------------------------------------
extern "C" void kernel_launch(void* const* d_in, const int* in_sizes, int n_in,
                              void* d_out, int out_size)
{
    const float* x      = (const float*)d_in[0];
    const float* wq     = (const float*)d_in[1];
    const float* wk     = (const float*)d_in[2];
    const float* wv     = (const float*)d_in[3];
    const float* w_proj = (const float*)d_in[4];
    const float* b_proj = (const float*)d_in[5];
    const float* w1     = (const float*)d_in[6];
    const float* b1     = (const float*)d_in[7];
    const float* w2     = (const float*)d_in[8];
    const float* b2     = (const float*)d_in[9];
    const float* g1     = (const float*)d_in[10];
    const float* be1    = (const float*)d_in[11];
    const float* g2     = (const float*)d_in[12];
    const float* be2    = (const float*)d_in[13];
    float* out = (float*)d_out;

    __half *ln1h, *qkvh, *atth, *x2h, *ln2h, *hidh, *wqkvh, *wph, *w1t, *w2t;
    cudaGetSymbolAddress((void**)&ln1h,  g_ln1h);
    cudaGetSymbolAddress((void**)&qkvh,  g_qkvh);
    cudaGetSymbolAddress((void**)&atth,  g_atth);
    cudaGetSymbolAddress((void**)&x2h,   g_x2h);
    cudaGetSymbolAddress((void**)&ln2h,  g_ln2h);
    cudaGetSymbolAddress((void**)&hidh,  g_hidh);
    cudaGetSymbolAddress((void**)&wqkvh, g_wqkv);
    cudaGetSymbolAddress((void**)&wph,   g_wp);
    cudaGetSymbolAddress((void**)&w1t,   g_w1t);
    cudaGetSymbolAddress((void**)&w2t,   g_w2t);

    cudaFuncSetAttribute(attn_mma_kernel,
                         cudaFuncAttributeMaxDynamicSharedMemorySize, ATTN_SMEM);
    cudaFuncSetAttribute(gemm_mma<0, 1, 0>,
                         cudaFuncAttributeMaxDynamicSharedMemorySize, GEMM_SMEM);
    cudaFuncSetAttribute(gemm_mma<0, 0, 1>,
                         cudaFuncAttributeMaxDynamicSharedMemorySize, GEMM_SMEM);
    cudaFuncSetAttribute(gemm_mma<1, 0, 1>,
                         cudaFuncAttributeMaxDynamicSharedMemorySize, GEMM_SMEM);

    // 1) Prep: all weight transposes + LN1 (f16 out) in one launch
    prep_kernel<<<PREP_TOTAL, 256>>>(wq, wk, wv, w_proj, w1, w2,
                                     wqkvh, wph, w1t, w2t,
                                     x, g1, be1, ln1h);

    // 2) QKV GEMM: [8192,1024] @ [3072,1024]^T -> f16
    gemm_mma<0, 0, 1><<<dim3(kQKVN / 128, kM / 128), 256, GEMM_SMEM>>>(
        ln1h, wqkvh, nullptr, nullptr, nullptr, qkvh, kM, kQKVN, kD);

    // 3) Causal flash attention (f16 HMMA) -> f16
    attn_mma_kernel<<<dim3(kT / 128, kH, kB), 256, ATTN_SMEM>>>(qkvh, atth);

    // 4) Output projection + bias + residual(ln1h) -> x2 (f16)
    gemm_mma<0, 0, 1><<<dim3(kD / 128, kM / 128), 256, GEMM_SMEM>>>(
        atth, wph, b_proj, ln1h, nullptr, x2h, kM, kD, kD);

    // 5) LN2 (f16 in, f16 out)
    ln_h_kernel<<<kM, 256>>>(x2h, g2, be2, ln2h);

    // 6) FFN1 + ReLU -> f16 hidden
    gemm_mma<1, 0, 1><<<dim3(kF / 128, kM / 128), 256, GEMM_SMEM>>>(
        ln2h, w1t, b1, nullptr, nullptr, hidh, kM, kF, kD);

    // 7) FFN2 + bias + residual(ln2h) -> output (f32)
    gemm_mma<0, 1, 0><<<dim3(kD / 128, kM / 128), 256, GEMM_SMEM>>>(
        hidh, w2t, b2, ln2h, out, nullptr, kM, kD, kF);
}